// round 2
// baseline (speedup 1.0000x reference)
#include <cuda_runtime.h>
#include <math.h>

#define Bb 16
#define Nn 1024
#define Dd 768
#define Hh 12
#define HS 64
#define ROWS (Bb*Nn)          // 16384
#define TOT  (Bb*Nn*Dd)       // 12,582,912
#define EPS  1e-6f

// scratch (no allocations allowed)
__device__ float g_xn[TOT];
__device__ float g_v[TOT];
__device__ float g_x2[TOT];   // x + y (residual)
__device__ float g_t[TOT];
__device__ float g_z[TOT];
__device__ float g_Wcat[Dd*Dd];

// ---------------- repack Wv[h][d][k] -> Wcat[d][h*HS+k] ----------------
__global__ void repack_wv_k(const float* __restrict__ Wv) {
    int idx = blockIdx.x * 256 + threadIdx.x;
    if (idx >= Dd * Dd) return;
    int col = idx % Dd;            // h*HS + k
    int d   = idx / Dd;
    int h = col / HS, k = col % HS;
    g_Wcat[idx] = Wv[((size_t)h * Dd + d) * HS + k];
}

// ---------------- layernorm (+ optional swish) ----------------
__inline__ __device__ float warpsum(float v) {
    #pragma unroll
    for (int o = 16; o; o >>= 1) v += __shfl_xor_sync(0xffffffffu, v, o);
    return v;
}

template <int ACT>
__global__ __launch_bounds__(256) void ln_k(const float* __restrict__ in,
                                            const float* __restrict__ sc,
                                            const float* __restrict__ bi,
                                            float* __restrict__ out) {
    int row = blockIdx.x;
    const float* r = in + (size_t)row * Dd;
    int t = threadIdx.x;
    float v0 = r[t], v1 = r[t + 256], v2 = r[t + 512];
    float s = v0 + v1 + v2;
    float q = v0 * v0 + v1 * v1 + v2 * v2;
    __shared__ float sh[16];
    float ws = warpsum(s), wq = warpsum(q);
    int w = t >> 5, l = t & 31;
    if (l == 0) { sh[w] = ws; sh[8 + w] = wq; }
    __syncthreads();
    float ssum = 0.f, ssq = 0.f;
    #pragma unroll
    for (int i = 0; i < 8; i++) { ssum += sh[i]; ssq += sh[8 + i]; }
    float mean = ssum * (1.0f / Dd);
    float var  = ssq * (1.0f / Dd) - mean * mean;
    float inv  = rsqrtf(var + EPS);
    float* o = out + (size_t)row * Dd;
    #pragma unroll
    for (int kk = 0; kk < 3; kk++) {
        int c = t + kk * 256;
        float v = (kk == 0 ? v0 : (kk == 1 ? v1 : v2));
        float val = (v - mean) * inv * sc[c] + bi[c];
        if (ACT) val = val / (1.0f + expf(-val));   // swish
        o[c] = val;
    }
}

// ---------------- SGEMM 128x128x8, 8x8 per thread, optional bias ----------------
__global__ __launch_bounds__(256) void sgemm_k(const float* __restrict__ A,
                                               const float* __restrict__ Bm,
                                               const float* __restrict__ bias,
                                               float* __restrict__ Cm,
                                               int M, int N, int K) {
    __shared__ float As[8][128];
    __shared__ float Bs[8][128];
    int tid = threadIdx.x;
    int tx = tid & 15, ty = tid >> 4;
    int arow = tid >> 1,  ak = (tid & 1) * 4;
    int brow = tid >> 5,  bc = (tid & 31) * 4;
    const float* Ag = A + (size_t)(blockIdx.y * 128 + arow) * K + ak;
    const float* Bg = Bm + (size_t)brow * N + blockIdx.x * 128 + bc;

    float acc[8][8];
    #pragma unroll
    for (int i = 0; i < 8; i++)
        #pragma unroll
        for (int j = 0; j < 8; j++) acc[i][j] = 0.f;

    for (int k0 = 0; k0 < K; k0 += 8) {
        float4 av = *(const float4*)(Ag + k0);
        float4 bv = *(const float4*)(Bg + (size_t)k0 * N);
        __syncthreads();
        As[ak + 0][arow] = av.x;
        As[ak + 1][arow] = av.y;
        As[ak + 2][arow] = av.z;
        As[ak + 3][arow] = av.w;
        *(float4*)&Bs[brow][bc] = bv;
        __syncthreads();
        #pragma unroll
        for (int k = 0; k < 8; k++) {
            float ar[8], br[8];
            *(float4*)(ar)     = *(float4*)&As[k][ty * 8];
            *(float4*)(ar + 4) = *(float4*)&As[k][ty * 8 + 4];
            *(float4*)(br)     = *(float4*)&Bs[k][tx * 8];
            *(float4*)(br + 4) = *(float4*)&Bs[k][tx * 8 + 4];
            #pragma unroll
            for (int i = 0; i < 8; i++)
                #pragma unroll
                for (int j = 0; j < 8; j++)
                    acc[i][j] = fmaf(ar[i], br[j], acc[i][j]);
        }
    }

    int row0 = blockIdx.y * 128 + ty * 8;
    int col0 = blockIdx.x * 128 + tx * 8;
    #pragma unroll
    for (int i = 0; i < 8; i++) {
        #pragma unroll
        for (int j4 = 0; j4 < 8; j4 += 4) {
            float4 o;
            float b0 = bias ? bias[col0 + j4 + 0] : 0.f;
            float b1 = bias ? bias[col0 + j4 + 1] : 0.f;
            float b2 = bias ? bias[col0 + j4 + 2] : 0.f;
            float b3 = bias ? bias[col0 + j4 + 3] : 0.f;
            o.x = acc[i][j4 + 0] + b0;
            o.y = acc[i][j4 + 1] + b1;
            o.z = acc[i][j4 + 2] + b2;
            o.w = acc[i][j4 + 3] + b3;
            *(float4*)&Cm[(size_t)(row0 + i) * N + col0 + j4] = o;
        }
    }
}

// ---------------- circulant mix: y[b,i,h,k] = sum_j alpha[h,(i-j)%N] v[b,j,h,k]; out = x + y ----------------
__global__ __launch_bounds__(256) void circ_k(const float* __restrict__ alpha,
                                              const float* __restrict__ x) {
    int i0 = blockIdx.x * 64;
    int h  = blockIdx.y;
    int b  = blockIdx.z;
    __shared__ float vs[64][68];
    __shared__ float as_[128];
    int tid = threadIdx.x;
    int ci = tid & 15, ri = tid >> 4;     // 4 cols x 4 rows per thread
    float acc[4][4];
    #pragma unroll
    for (int a = 0; a < 4; a++)
        #pragma unroll
        for (int c = 0; c < 4; c++) acc[a][c] = 0.f;

    for (int j0 = 0; j0 < Nn; j0 += 64) {
        __syncthreads();
        // v tile: 64 rows x 64 cols (this head's slice)
        #pragma unroll
        for (int t = tid; t < 64 * 16; t += 256) {
            int jj = t >> 4;
            int c4 = (t & 15) * 4;
            *(float4*)&vs[jj][c4] =
                *(const float4*)&g_v[((size_t)(b * Nn + j0 + jj)) * Dd + h * HS + c4];
        }
        // alpha window: indices (i - j) mod N for i in [i0,i0+64), j in [j0,j0+64)
        if (tid < 127) {
            int idx = i0 - j0 - 63 + tid;
            idx &= (Nn - 1);   // N is power of 2
            as_[tid] = alpha[h * Nn + idx];
        }
        __syncthreads();
        #pragma unroll 8
        for (int jj = 0; jj < 64; jj++) {
            float4 bb = *(float4*)&vs[jj][ci * 4];
            #pragma unroll
            for (int a = 0; a < 4; a++) {
                float av = as_[ri * 4 + a - jj + 63];
                acc[a][0] = fmaf(av, bb.x, acc[a][0]);
                acc[a][1] = fmaf(av, bb.y, acc[a][1]);
                acc[a][2] = fmaf(av, bb.z, acc[a][2]);
                acc[a][3] = fmaf(av, bb.w, acc[a][3]);
            }
        }
    }
    // residual add + store
    #pragma unroll
    for (int a = 0; a < 4; a++) {
        size_t off = ((size_t)(b * Nn + i0 + ri * 4 + a)) * Dd + h * HS + ci * 4;
        float4 xv = *(const float4*)&x[off];
        float4 o;
        o.x = acc[a][0] + xv.x;
        o.y = acc[a][1] + xv.y;
        o.z = acc[a][2] + xv.z;
        o.w = acc[a][3] + xv.w;
        *(float4*)&g_x2[off] = o;
    }
}

// ---------------- final: out = log_cosh(z + x2) ----------------
__global__ __launch_bounds__(256) void final_k(float* __restrict__ out) {
    int i = blockIdx.x * 256 + threadIdx.x;
    float v = g_z[i] + g_x2[i];
    float a = fabsf(v);
    out[i] = a + log1pf(expf(-2.0f * a)) - 0.69314718055994530942f;
}

extern "C" void kernel_launch(void* const* d_in, const int* in_sizes, int n_in,
                              void* d_out, int out_size) {
    const float* x         = (const float*)d_in[0];
    const float* ln1_scale = (const float*)d_in[1];
    const float* ln1_bias  = (const float*)d_in[2];
    const float* Wv        = (const float*)d_in[3];
    const float* alpha     = (const float*)d_in[4];
    const float* Wf        = (const float*)d_in[5];
    const float* bf        = (const float*)d_in[6];
    const float* lnf_scale = (const float*)d_in[7];
    const float* lnf_bias  = (const float*)d_in[8];
    float* out = (float*)d_out;

    float *xn, *v, *x2, *t, *z, *wcat;
    cudaGetSymbolAddress((void**)&xn,   g_xn);
    cudaGetSymbolAddress((void**)&v,    g_v);
    cudaGetSymbolAddress((void**)&x2,   g_x2);
    cudaGetSymbolAddress((void**)&t,    g_t);
    cudaGetSymbolAddress((void**)&z,    g_z);
    cudaGetSymbolAddress((void**)&wcat, g_Wcat);

    // 1. repack Wv -> Wcat
    repack_wv_k<<<(Dd * Dd + 255) / 256, 256>>>(Wv);
    // 2. xn = LN(x)
    ln_k<0><<<ROWS, 256>>>(x, ln1_scale, ln1_bias, xn);
    // 3. v = xn @ Wcat
    sgemm_k<<<dim3(Dd / 128, ROWS / 128), 256>>>(xn, wcat, nullptr, v, ROWS, Dd, Dd);
    // 4. x2 = x + circulant(alpha) * v
    circ_k<<<dim3(Nn / 64, Hh, Bb), 256>>>(alpha, x);
    // 5. FFN layer 0: t = x2 @ Wf[0] + bf[0]; z = swish(LN(t))
    sgemm_k<<<dim3(Dd / 128, ROWS / 128), 256>>>(x2, Wf, bf, t, ROWS, Dd, Dd);
    ln_k<1><<<ROWS, 256>>>(t, lnf_scale, lnf_bias, z);
    // 6. FFN layer 1
    sgemm_k<<<dim3(Dd / 128, ROWS / 128), 256>>>(z, Wf + (size_t)Dd * Dd, bf + Dd, t, ROWS, Dd, Dd);
    ln_k<1><<<ROWS, 256>>>(t, lnf_scale + Dd, lnf_bias + Dd, z);
    // 7. out = log_cosh(z + x2)
    final_k<<<TOT / 256, 256>>>(out);
}

// round 3
// speedup vs baseline: 1.0320x; 1.0320x over previous
#include <cuda_runtime.h>
#include <math.h>

#define Bb 16
#define Nn 1024
#define Dd 768
#define Hh 12
#define HS 64
#define ROWS (Bb*Nn)          // 16384
#define TOT  (Bb*Nn*Dd)       // 12,582,912
#define EPS  1e-6f

typedef unsigned long long u64;

// scratch (no allocations allowed)
__device__ float g_xn[TOT];
__device__ float g_v[TOT];
__device__ float g_x2[TOT];   // x + y (residual)
__device__ float g_t[TOT];
__device__ float g_z[TOT];
__device__ float g_Wcat[Dd*Dd];

// ---------------- packed f32x2 helpers ----------------
__device__ __forceinline__ u64 pk2(float x) {
    u64 r;
    unsigned u = __float_as_uint(x);
    asm("mov.b64 %0, {%1, %1};" : "=l"(r) : "r"(u));
    return r;
}
__device__ __forceinline__ void fma2(u64& d, u64 a, u64 b) {
    asm("fma.rn.f32x2 %0, %1, %2, %3;" : "=l"(d) : "l"(a), "l"(b), "l"(d));
}
__device__ __forceinline__ float2 up2(u64 v) {
    float2 r;
    asm("mov.b64 {%0, %1}, %2;" : "=f"(r.x), "=f"(r.y) : "l"(v));
    return r;
}

// ---------------- repack Wv[h][d][k] -> Wcat[d][h*HS+k] ----------------
__global__ void repack_wv_k(const float* __restrict__ Wv) {
    int idx = blockIdx.x * 256 + threadIdx.x;
    if (idx >= Dd * Dd) return;
    int col = idx % Dd;            // h*HS + k
    int d   = idx / Dd;
    int h = col / HS, k = col % HS;
    g_Wcat[idx] = Wv[((size_t)h * Dd + d) * HS + k];
}

// ---------------- layernorm (+ optional swish) ----------------
__inline__ __device__ float warpsum(float v) {
    #pragma unroll
    for (int o = 16; o; o >>= 1) v += __shfl_xor_sync(0xffffffffu, v, o);
    return v;
}

template <int ACT>
__global__ __launch_bounds__(256) void ln_k(const float* __restrict__ in,
                                            const float* __restrict__ sc,
                                            const float* __restrict__ bi,
                                            float* __restrict__ out) {
    int row = blockIdx.x;
    const float* r = in + (size_t)row * Dd;
    int t = threadIdx.x;
    float v0 = r[t], v1 = r[t + 256], v2 = r[t + 512];
    float s = v0 + v1 + v2;
    float q = v0 * v0 + v1 * v1 + v2 * v2;
    __shared__ float sh[16];
    float ws = warpsum(s), wq = warpsum(q);
    int w = t >> 5, l = t & 31;
    if (l == 0) { sh[w] = ws; sh[8 + w] = wq; }
    __syncthreads();
    float ssum = 0.f, ssq = 0.f;
    #pragma unroll
    for (int i = 0; i < 8; i++) { ssum += sh[i]; ssq += sh[8 + i]; }
    float mean = ssum * (1.0f / Dd);
    float var  = ssq * (1.0f / Dd) - mean * mean;
    float inv  = rsqrtf(var + EPS);
    float* o = out + (size_t)row * Dd;
    #pragma unroll
    for (int kk = 0; kk < 3; kk++) {
        int c = t + kk * 256;
        float v = (kk == 0 ? v0 : (kk == 1 ? v1 : v2));
        float val = (v - mean) * inv * sc[c] + bi[c];
        if (ACT) val = val / (1.0f + expf(-val));   // swish
        o[c] = val;
    }
}

// ---------------- SGEMM 128x128x8, 8x8 per thread via f32x2, optional bias ----------------
__global__ __launch_bounds__(256) void sgemm_k(const float* __restrict__ A,
                                               const float* __restrict__ Bm,
                                               const float* __restrict__ bias,
                                               float* __restrict__ Cm,
                                               int M, int N, int K) {
    __shared__ float As[8][128];
    __shared__ float Bs[8][128];
    int tid = threadIdx.x;
    int tx = tid & 15, ty = tid >> 4;
    int arow = tid >> 1,  ak = (tid & 1) * 4;
    int brow = tid >> 5,  bc = (tid & 31) * 4;
    const float* Ag = A + (size_t)(blockIdx.y * 128 + arow) * K + ak;
    const float* Bg = Bm + (size_t)brow * N + blockIdx.x * 128 + bc;

    u64 acc[8][4];
    #pragma unroll
    for (int i = 0; i < 8; i++)
        #pragma unroll
        for (int j = 0; j < 4; j++) acc[i][j] = 0ull;

    for (int k0 = 0; k0 < K; k0 += 8) {
        float4 av = *(const float4*)(Ag + k0);
        float4 bv = *(const float4*)(Bg + (size_t)k0 * N);
        __syncthreads();
        As[ak + 0][arow] = av.x;
        As[ak + 1][arow] = av.y;
        As[ak + 2][arow] = av.z;
        As[ak + 3][arow] = av.w;
        *(float4*)&Bs[brow][bc] = bv;
        __syncthreads();
        #pragma unroll
        for (int k = 0; k < 8; k++) {
            float ar[8];
            *(float4*)(ar)     = *(float4*)&As[k][ty * 8];
            *(float4*)(ar + 4) = *(float4*)&As[k][ty * 8 + 4];
            ulonglong2 b01 = *(const ulonglong2*)&Bs[k][tx * 8];
            ulonglong2 b23 = *(const ulonglong2*)&Bs[k][tx * 8 + 4];
            #pragma unroll
            for (int i = 0; i < 8; i++) {
                u64 a2 = pk2(ar[i]);
                fma2(acc[i][0], a2, b01.x);
                fma2(acc[i][1], a2, b01.y);
                fma2(acc[i][2], a2, b23.x);
                fma2(acc[i][3], a2, b23.y);
            }
        }
    }

    int row0 = blockIdx.y * 128 + ty * 8;
    int col0 = blockIdx.x * 128 + tx * 8;
    #pragma unroll
    for (int i = 0; i < 8; i++) {
        #pragma unroll
        for (int j2 = 0; j2 < 4; j2 += 2) {
            float2 p0 = up2(acc[i][j2]);
            float2 p1 = up2(acc[i][j2 + 1]);
            int c = col0 + j2 * 2;
            float4 o;
            o.x = p0.x; o.y = p0.y; o.z = p1.x; o.w = p1.y;
            if (bias) {
                o.x += bias[c + 0]; o.y += bias[c + 1];
                o.z += bias[c + 2]; o.w += bias[c + 3];
            }
            *(float4*)&Cm[(size_t)(row0 + i) * N + c] = o;
        }
    }
}

// ---------------- circulant mix: y[b,i,h,k] = sum_j alpha[h,(i-j)%N] v[b,j,h,k]; out = x + y ----------------
__global__ __launch_bounds__(256) void circ_k(const float* __restrict__ alpha,
                                              const float* __restrict__ x) {
    int i0 = blockIdx.x * 64;
    int h  = blockIdx.y;
    int b  = blockIdx.z;
    __shared__ float vs[64][68];
    __shared__ float as_[128];
    int tid = threadIdx.x;
    int ci = tid & 15, ri = tid >> 4;     // 4 cols x 4 rows per thread
    u64 acc[4][2];
    #pragma unroll
    for (int a = 0; a < 4; a++) { acc[a][0] = 0ull; acc[a][1] = 0ull; }

    for (int j0 = 0; j0 < Nn; j0 += 64) {
        __syncthreads();
        // v tile: 64 rows x 64 cols (this head's slice)
        #pragma unroll
        for (int t = tid; t < 64 * 16; t += 256) {
            int jj = t >> 4;
            int c4 = (t & 15) * 4;
            *(float4*)&vs[jj][c4] =
                *(const float4*)&g_v[((size_t)(b * Nn + j0 + jj)) * Dd + h * HS + c4];
        }
        // alpha window: indices (i - j) mod N for i in [i0,i0+64), j in [j0,j0+64)
        if (tid < 127) {
            int idx = i0 - j0 - 63 + tid;
            idx &= (Nn - 1);   // N is power of 2
            as_[tid] = alpha[h * Nn + idx];
        }
        __syncthreads();
        #pragma unroll 8
        for (int jj = 0; jj < 64; jj++) {
            ulonglong2 bb = *(const ulonglong2*)&vs[jj][ci * 4];
            #pragma unroll
            for (int a = 0; a < 4; a++) {
                u64 av2 = pk2(as_[ri * 4 + a - jj + 63]);
                fma2(acc[a][0], av2, bb.x);
                fma2(acc[a][1], av2, bb.y);
            }
        }
    }
    // residual add + store
    #pragma unroll
    for (int a = 0; a < 4; a++) {
        size_t off = ((size_t)(b * Nn + i0 + ri * 4 + a)) * Dd + h * HS + ci * 4;
        float4 xv = *(const float4*)&x[off];
        float2 p0 = up2(acc[a][0]);
        float2 p1 = up2(acc[a][1]);
        float4 o;
        o.x = p0.x + xv.x;
        o.y = p0.y + xv.y;
        o.z = p1.x + xv.z;
        o.w = p1.y + xv.w;
        *(float4*)&g_x2[off] = o;
    }
}

// ---------------- final: out = log_cosh(z + x2) ----------------
__global__ __launch_bounds__(256) void final_k(float* __restrict__ out) {
    int i = blockIdx.x * 256 + threadIdx.x;
    float v = g_z[i] + g_x2[i];
    float a = fabsf(v);
    out[i] = a + log1pf(expf(-2.0f * a)) - 0.69314718055994530942f;
}

extern "C" void kernel_launch(void* const* d_in, const int* in_sizes, int n_in,
                              void* d_out, int out_size) {
    const float* x         = (const float*)d_in[0];
    const float* ln1_scale = (const float*)d_in[1];
    const float* ln1_bias  = (const float*)d_in[2];
    const float* Wv        = (const float*)d_in[3];
    const float* alpha     = (const float*)d_in[4];
    const float* Wf        = (const float*)d_in[5];
    const float* bf        = (const float*)d_in[6];
    const float* lnf_scale = (const float*)d_in[7];
    const float* lnf_bias  = (const float*)d_in[8];
    float* out = (float*)d_out;

    float *xn, *v, *x2, *t, *z, *wcat;
    cudaGetSymbolAddress((void**)&xn,   g_xn);
    cudaGetSymbolAddress((void**)&v,    g_v);
    cudaGetSymbolAddress((void**)&x2,   g_x2);
    cudaGetSymbolAddress((void**)&t,    g_t);
    cudaGetSymbolAddress((void**)&z,    g_z);
    cudaGetSymbolAddress((void**)&wcat, g_Wcat);

    // 1. repack Wv -> Wcat
    repack_wv_k<<<(Dd * Dd + 255) / 256, 256>>>(Wv);
    // 2. xn = LN(x)
    ln_k<0><<<ROWS, 256>>>(x, ln1_scale, ln1_bias, xn);
    // 3. v = xn @ Wcat
    sgemm_k<<<dim3(Dd / 128, ROWS / 128), 256>>>(xn, wcat, nullptr, v, ROWS, Dd, Dd);
    // 4. x2 = x + circulant(alpha) * v
    circ_k<<<dim3(Nn / 64, Hh, Bb), 256>>>(alpha, x);
    // 5. FFN layer 0: t = x2 @ Wf[0] + bf[0]; z = swish(LN(t))
    sgemm_k<<<dim3(Dd / 128, ROWS / 128), 256>>>(x2, Wf, bf, t, ROWS, Dd, Dd);
    ln_k<1><<<ROWS, 256>>>(t, lnf_scale, lnf_bias, z);
    // 6. FFN layer 1
    sgemm_k<<<dim3(Dd / 128, ROWS / 128), 256>>>(z, Wf + (size_t)Dd * Dd, bf + Dd, t, ROWS, Dd, Dd);
    ln_k<1><<<ROWS, 256>>>(t, lnf_scale + Dd, lnf_bias + Dd, z);
    // 7. out = log_cosh(z + x2)
    final_k<<<TOT / 256, 256>>>(out);
}

// round 4
// speedup vs baseline: 1.5026x; 1.4561x over previous
#include <cuda_runtime.h>
#include <cuda_bf16.h>
#include <math.h>

#define Bb 16
#define Nn 1024
#define Dd 768
#define Hh 12
#define HS 64
#define ROWS (Bb*Nn)          // 16384
#define TOT  (Bb*Nn*Dd)       // 12,582,912
#define D2   (Dd*Dd)
#define EPS  1e-6f

typedef unsigned long long u64;
typedef unsigned int u32;

// scratch (no allocations allowed)
__device__ float g_v[TOT];
__device__ float g_x2[TOT];
__device__ float g_t[TOT];
__device__ float g_z[TOT];
__device__ __nv_bfloat16 g_ah[TOT];       // activation split hi (reused xn -> x2 -> z0)
__device__ __nv_bfloat16 g_al[TOT];       // activation split lo
__device__ __nv_bfloat16 g_wh[3*D2];      // weights split hi: [wcat, wf0, wf1]
__device__ __nv_bfloat16 g_wl[3*D2];

// ---------------- helpers ----------------
__device__ __forceinline__ void split2(float x, __nv_bfloat16& h, __nv_bfloat16& l) {
    h = __float2bfloat16(x);
    l = __float2bfloat16(x - __bfloat162float(h));
}
__device__ __forceinline__ u32 smem_u32(const void* p) {
    return (u32)__cvta_generic_to_shared(p);
}
__device__ __forceinline__ void ldm_x4(u32 r[4], u32 addr) {
    asm volatile("ldmatrix.sync.aligned.m8n8.x4.shared.b16 {%0,%1,%2,%3}, [%4];"
                 : "=r"(r[0]), "=r"(r[1]), "=r"(r[2]), "=r"(r[3]) : "r"(addr));
}
__device__ __forceinline__ void ldm_x4_t(u32 r[4], u32 addr) {
    asm volatile("ldmatrix.sync.aligned.m8n8.x4.trans.shared.b16 {%0,%1,%2,%3}, [%4];"
                 : "=r"(r[0]), "=r"(r[1]), "=r"(r[2]), "=r"(r[3]) : "r"(addr));
}
__device__ __forceinline__ void mma_bf16(float c[4], const u32 a[4], u32 b0, u32 b1) {
    asm volatile("mma.sync.aligned.m16n8k16.row.col.f32.bf16.bf16.f32 "
                 "{%0,%1,%2,%3}, {%4,%5,%6,%7}, {%8,%9}, {%0,%1,%2,%3};"
                 : "+f"(c[0]), "+f"(c[1]), "+f"(c[2]), "+f"(c[3])
                 : "r"(a[0]), "r"(a[1]), "r"(a[2]), "r"(a[3]), "r"(b0), "r"(b1));
}

// ---------------- weight prep ----------------
__global__ void wsplit_wv_k(const float* __restrict__ Wv) {
    int idx = blockIdx.x * 256 + threadIdx.x;
    if (idx >= D2) return;
    int col = idx % Dd;
    int d   = idx / Dd;
    int h = col / HS, k = col % HS;
    float v = Wv[((size_t)h * Dd + d) * HS + k];
    split2(v, g_wh[idx], g_wl[idx]);
}
__global__ void wsplit_wf_k(const float* __restrict__ Wf) {
    int idx = blockIdx.x * 256 + threadIdx.x;
    if (idx >= 2 * D2) return;
    split2(Wf[idx], g_wh[D2 + idx], g_wl[D2 + idx]);
}

// ---------------- layernorm (+swish) ----------------
__inline__ __device__ float warpsum(float v) {
    #pragma unroll
    for (int o = 16; o; o >>= 1) v += __shfl_xor_sync(0xffffffffu, v, o);
    return v;
}

template <int ACT, int WSPLIT, int WF32>
__global__ __launch_bounds__(256) void ln_k(const float* __restrict__ in,
                                            const float* __restrict__ sc,
                                            const float* __restrict__ bi,
                                            float* __restrict__ outf) {
    int row = blockIdx.x;
    const float* r = in + (size_t)row * Dd;
    int t = threadIdx.x;
    float v0 = r[t], v1 = r[t + 256], v2 = r[t + 512];
    float s = v0 + v1 + v2;
    float q = v0 * v0 + v1 * v1 + v2 * v2;
    __shared__ float sh[16];
    float ws = warpsum(s), wq = warpsum(q);
    int w = t >> 5, l = t & 31;
    if (l == 0) { sh[w] = ws; sh[8 + w] = wq; }
    __syncthreads();
    float ssum = 0.f, ssq = 0.f;
    #pragma unroll
    for (int i = 0; i < 8; i++) { ssum += sh[i]; ssq += sh[8 + i]; }
    float mean = ssum * (1.0f / Dd);
    float var  = ssq * (1.0f / Dd) - mean * mean;
    float inv  = rsqrtf(var + EPS);
    #pragma unroll
    for (int kk = 0; kk < 3; kk++) {
        int c = t + kk * 256;
        float v = (kk == 0 ? v0 : (kk == 1 ? v1 : v2));
        float val = (v - mean) * inv * sc[c] + bi[c];
        if (ACT) val = val / (1.0f + expf(-val));
        size_t off = (size_t)row * Dd + c;
        if (WSPLIT) split2(val, g_ah[off], g_al[off]);
        if (WF32) outf[off] = val;
    }
}

// ---------------- tensor-core GEMM: C = [g_ah,g_al] @ [Bh,Bl] (+bias) ----------------
__global__ __launch_bounds__(256) void gemm_bf16(const __nv_bfloat16* __restrict__ Bh,
                                                 const __nv_bfloat16* __restrict__ Bl,
                                                 const float* __restrict__ bias,
                                                 float* __restrict__ C,
                                                 int M, int N, int K) {
    __shared__ __nv_bfloat16 As[2][128][40];
    __shared__ __nv_bfloat16 Bs[2][32][136];
    int tid = threadIdx.x;
    int wid = tid >> 5, lane = tid & 31;
    int wm = (wid & 3) * 32;
    int wn = (wid >> 2) * 64;
    int bm0 = blockIdx.y * 128;
    int bn0 = blockIdx.x * 128;

    float acc[16][4];
    #pragma unroll
    for (int i = 0; i < 16; i++)
        #pragma unroll
        for (int j = 0; j < 4; j++) acc[i][j] = 0.f;

    int mi = lane >> 3;
    int mr = lane & 7;

    for (int kt = 0; kt < K; kt += 32) {
        __syncthreads();
        #pragma unroll
        for (int c = tid; c < 512; c += 256) {
            int r = c >> 2, co = (c & 3) * 8;
            size_t g = (size_t)(bm0 + r) * K + kt + co;
            *(uint4*)&As[0][r][co] = *(const uint4*)&g_ah[g];
            *(uint4*)&As[1][r][co] = *(const uint4*)&g_al[g];
        }
        #pragma unroll
        for (int c = tid; c < 512; c += 256) {
            int r = c >> 4, co = (c & 15) * 8;
            size_t g = (size_t)(kt + r) * N + bn0 + co;
            *(uint4*)&Bs[0][r][co] = *(const uint4*)&Bh[g];
            *(uint4*)&Bs[1][r][co] = *(const uint4*)&Bl[g];
        }
        __syncthreads();

        #pragma unroll
        for (int ks = 0; ks < 32; ks += 16) {
            u32 aH[2][4], aL[2][4];
            #pragma unroll
            for (int mt = 0; mt < 2; mt++) {
                int row = wm + mt * 16 + (mi & 1) * 8 + mr;
                int col = ks + (mi >> 1) * 8;
                ldm_x4(aH[mt], smem_u32(&As[0][row][col]));
                ldm_x4(aL[mt], smem_u32(&As[1][row][col]));
            }
            #pragma unroll
            for (int t = 0; t < 4; t++) {
                u32 bH[4], bL[4];
                int brow = ks + (mi & 1) * 8 + mr;
                int bcol = wn + t * 16 + (mi >> 1) * 8;
                ldm_x4_t(bH, smem_u32(&Bs[0][brow][bcol]));
                ldm_x4_t(bL, smem_u32(&Bs[1][brow][bcol]));
                #pragma unroll
                for (int mt = 0; mt < 2; mt++) {
                    #pragma unroll
                    for (int h2 = 0; h2 < 2; h2++) {
                        float* c = acc[mt * 8 + t * 2 + h2];
                        mma_bf16(c, aH[mt], bH[h2 * 2], bH[h2 * 2 + 1]);
                        mma_bf16(c, aH[mt], bL[h2 * 2], bL[h2 * 2 + 1]);
                        mma_bf16(c, aL[mt], bH[h2 * 2], bH[h2 * 2 + 1]);
                    }
                }
            }
        }
    }

    int qr = lane >> 2;
    int qc = (lane & 3) * 2;
    #pragma unroll
    for (int mt = 0; mt < 2; mt++) {
        #pragma unroll
        for (int nt = 0; nt < 8; nt++) {
            float* c = acc[mt * 8 + nt];
            int row = bm0 + wm + mt * 16 + qr;
            int col = bn0 + wn + nt * 8 + qc;
            float b0 = 0.f, b1 = 0.f;
            if (bias) { b0 = bias[col]; b1 = bias[col + 1]; }
            float2 o0 = make_float2(c[0] + b0, c[1] + b1);
            float2 o1 = make_float2(c[2] + b0, c[3] + b1);
            *(float2*)&C[(size_t)row * N + col] = o0;
            *(float2*)&C[(size_t)(row + 8) * N + col] = o1;
        }
    }
}

// ---------------- packed f32x2 helpers (circ) ----------------
__device__ __forceinline__ u64 pk2(float x) {
    u64 r;
    unsigned u = __float_as_uint(x);
    asm("mov.b64 %0, {%1, %1};" : "=l"(r) : "r"(u));
    return r;
}
__device__ __forceinline__ void fma2(u64& d, u64 a, u64 b) {
    asm("fma.rn.f32x2 %0, %1, %2, %3;" : "=l"(d) : "l"(a), "l"(b), "l"(d));
}
__device__ __forceinline__ float2 up2(u64 v) {
    float2 r;
    asm("mov.b64 {%0, %1}, %2;" : "=f"(r.x), "=f"(r.y) : "l"(v));
    return r;
}

// ---------------- circulant mix + residual; emits x2 fp32 AND split ----------------
__global__ __launch_bounds__(256) void circ_k(const float* __restrict__ alpha,
                                              const float* __restrict__ x) {
    int i0 = blockIdx.x * 64;
    int h  = blockIdx.y;
    int b  = blockIdx.z;
    __shared__ float vs[64][68];
    __shared__ float as_[128];
    int tid = threadIdx.x;
    int ci = tid & 15, ri = tid >> 4;
    u64 acc[4][2];
    #pragma unroll
    for (int a = 0; a < 4; a++) { acc[a][0] = 0ull; acc[a][1] = 0ull; }

    for (int j0 = 0; j0 < Nn; j0 += 64) {
        __syncthreads();
        #pragma unroll
        for (int t = tid; t < 64 * 16; t += 256) {
            int jj = t >> 4;
            int c4 = (t & 15) * 4;
            *(float4*)&vs[jj][c4] =
                *(const float4*)&g_v[((size_t)(b * Nn + j0 + jj)) * Dd + h * HS + c4];
        }
        if (tid < 127) {
            int idx = (i0 - j0 - 63 + tid) & (Nn - 1);
            as_[tid] = alpha[h * Nn + idx];
        }
        __syncthreads();
        #pragma unroll 8
        for (int jj = 0; jj < 64; jj++) {
            ulonglong2 bb = *(const ulonglong2*)&vs[jj][ci * 4];
            #pragma unroll
            for (int a = 0; a < 4; a++) {
                u64 av2 = pk2(as_[ri * 4 + a - jj + 63]);
                fma2(acc[a][0], av2, bb.x);
                fma2(acc[a][1], av2, bb.y);
            }
        }
    }
    #pragma unroll
    for (int a = 0; a < 4; a++) {
        size_t off = ((size_t)(b * Nn + i0 + ri * 4 + a)) * Dd + h * HS + ci * 4;
        float4 xv = *(const float4*)&x[off];
        float2 p0 = up2(acc[a][0]);
        float2 p1 = up2(acc[a][1]);
        float4 o;
        o.x = p0.x + xv.x;
        o.y = p0.y + xv.y;
        o.z = p1.x + xv.z;
        o.w = p1.y + xv.w;
        *(float4*)&g_x2[off] = o;
        __nv_bfloat16 h0, l0, h1, l1, h2, l2, h3, l3;
        split2(o.x, h0, l0); split2(o.y, h1, l1);
        split2(o.z, h2, l2); split2(o.w, h3, l3);
        __nv_bfloat162 hp0, hp1, lp0, lp1;
        hp0.x = h0; hp0.y = h1; hp1.x = h2; hp1.y = h3;
        lp0.x = l0; lp0.y = l1; lp1.x = l2; lp1.y = l3;
        *(__nv_bfloat162*)&g_ah[off]     = hp0;
        *(__nv_bfloat162*)&g_ah[off + 2] = hp1;
        *(__nv_bfloat162*)&g_al[off]     = lp0;
        *(__nv_bfloat162*)&g_al[off + 2] = lp1;
    }
}

// ---------------- final ----------------
__global__ __launch_bounds__(256) void final_k(float* __restrict__ out) {
    int i = blockIdx.x * 256 + threadIdx.x;
    float v = g_z[i] + g_x2[i];
    float a = fabsf(v);
    out[i] = a + log1pf(expf(-2.0f * a)) - 0.69314718055994530942f;
}

extern "C" void kernel_launch(void* const* d_in, const int* in_sizes, int n_in,
                              void* d_out, int out_size) {
    const float* x         = (const float*)d_in[0];
    const float* ln1_scale = (const float*)d_in[1];
    const float* ln1_bias  = (const float*)d_in[2];
    const float* Wv        = (const float*)d_in[3];
    const float* alpha     = (const float*)d_in[4];
    const float* Wf        = (const float*)d_in[5];
    const float* bf        = (const float*)d_in[6];
    const float* lnf_scale = (const float*)d_in[7];
    const float* lnf_bias  = (const float*)d_in[8];
    float* out = (float*)d_out;

    float *v, *t, *z;
    __nv_bfloat16 *wh, *wl;
    cudaGetSymbolAddress((void**)&v,  g_v);
    cudaGetSymbolAddress((void**)&t,  g_t);
    cudaGetSymbolAddress((void**)&z,  g_z);
    cudaGetSymbolAddress((void**)&wh, g_wh);
    cudaGetSymbolAddress((void**)&wl, g_wl);

    dim3 ggrid(Dd / 128, ROWS / 128);

    wsplit_wv_k<<<(D2 + 255) / 256, 256>>>(Wv);
    wsplit_wf_k<<<(2 * D2 + 255) / 256, 256>>>(Wf);
    ln_k<0, 1, 0><<<ROWS, 256>>>(x, ln1_scale, ln1_bias, nullptr);
    gemm_bf16<<<ggrid, 256>>>(wh, wl, nullptr, v, ROWS, Dd, Dd);
    circ_k<<<dim3(Nn / 64, Hh, Bb), 256>>>(alpha, x);
    gemm_bf16<<<ggrid, 256>>>(wh + D2, wl + D2, bf, t, ROWS, Dd, Dd);
    ln_k<1, 1, 0><<<ROWS, 256>>>(t, lnf_scale, lnf_bias, nullptr);
    gemm_bf16<<<ggrid, 256>>>(wh + 2 * D2, wl + 2 * D2, bf + Dd, t, ROWS, Dd, Dd);
    ln_k<1, 0, 1><<<ROWS, 256>>>(t, lnf_scale + Dd, lnf_bias + Dd, z);
    final_k<<<TOT / 256, 256>>>(out);
}

// round 5
// speedup vs baseline: 2.3642x; 1.5734x over previous
#include <cuda_runtime.h>
#include <cuda_bf16.h>
#include <math.h>

#define Bb 16
#define Nn 1024
#define Dd 768
#define Hh 12
#define HS 64
#define ROWS (Bb*Nn)          // 16384
#define TOT  (Bb*Nn*Dd)       // 12,582,912
#define D2   (Dd*Dd)
#define EPS  1e-6f

typedef unsigned long long u64;
typedef unsigned int u32;
typedef __nv_bfloat16 bf16;

// scratch (no allocations allowed)
__device__ float g_x2[TOT];
__device__ float g_t[TOT];
__device__ bf16 g_vh[TOT];                // v split hi
__device__ bf16 g_vl[TOT];                // v split lo
__device__ bf16 g_ah[TOT];                // activation split hi (xn -> x2 -> z0)
__device__ bf16 g_al[TOT];                // activation split lo
__device__ bf16 g_wh[3*D2];               // weights hi: [wcat, wf0, wf1]
__device__ bf16 g_wl[3*D2];

// ---------------- helpers ----------------
__device__ __forceinline__ void split2(float x, bf16& h, bf16& l) {
    h = __float2bfloat16(x);
    l = __float2bfloat16(x - __bfloat162float(h));
}
__device__ __forceinline__ u32 pack_bf2(bf16 a, bf16 b) {
    __nv_bfloat162 p; p.x = a; p.y = b;
    return *reinterpret_cast<u32*>(&p);
}
__device__ __forceinline__ u32 smem_u32(const void* p) {
    return (u32)__cvta_generic_to_shared(p);
}
__device__ __forceinline__ void cpa16(u32 dst, const void* src) {
    asm volatile("cp.async.cg.shared.global [%0], [%1], 16;" :: "r"(dst), "l"(src));
}
#define CP_COMMIT() asm volatile("cp.async.commit_group;")
#define CP_WAIT(n)  asm volatile("cp.async.wait_group %0;" :: "n"(n))

__device__ __forceinline__ void ldm_x4(u32 r[4], u32 addr) {
    asm volatile("ldmatrix.sync.aligned.m8n8.x4.shared.b16 {%0,%1,%2,%3}, [%4];"
                 : "=r"(r[0]), "=r"(r[1]), "=r"(r[2]), "=r"(r[3]) : "r"(addr));
}
__device__ __forceinline__ void ldm_x4_t(u32 r[4], u32 addr) {
    asm volatile("ldmatrix.sync.aligned.m8n8.x4.trans.shared.b16 {%0,%1,%2,%3}, [%4];"
                 : "=r"(r[0]), "=r"(r[1]), "=r"(r[2]), "=r"(r[3]) : "r"(addr));
}
__device__ __forceinline__ void mma_bf16(float c[4], const u32 a[4], u32 b0, u32 b1) {
    asm volatile("mma.sync.aligned.m16n8k16.row.col.f32.bf16.bf16.f32 "
                 "{%0,%1,%2,%3}, {%4,%5,%6,%7}, {%8,%9}, {%0,%1,%2,%3};"
                 : "+f"(c[0]), "+f"(c[1]), "+f"(c[2]), "+f"(c[3])
                 : "r"(a[0]), "r"(a[1]), "r"(a[2]), "r"(a[3]), "r"(b0), "r"(b1));
}

// ---------------- weight prep ----------------
__global__ void wsplit_wv_k(const float* __restrict__ Wv) {
    int idx = blockIdx.x * 256 + threadIdx.x;
    if (idx >= D2) return;
    int col = idx % Dd;
    int d   = idx / Dd;
    int h = col / HS, k = col % HS;
    float v = Wv[((size_t)h * Dd + d) * HS + k];
    split2(v, g_wh[idx], g_wl[idx]);
}
__global__ void wsplit_wf_k(const float* __restrict__ Wf) {
    int idx = blockIdx.x * 256 + threadIdx.x;
    if (idx >= 2 * D2) return;
    split2(Wf[idx], g_wh[D2 + idx], g_wl[D2 + idx]);
}

// ---------------- layernorm (+swish) ----------------
__inline__ __device__ float warpsum(float v) {
    #pragma unroll
    for (int o = 16; o; o >>= 1) v += __shfl_xor_sync(0xffffffffu, v, o);
    return v;
}

// WSPLIT: write split to g_ah/g_al.  FINAL: out = log_cosh(val + x2)
template <int ACT, int WSPLIT, int FINAL>
__global__ __launch_bounds__(256) void ln_k(const float* __restrict__ in,
                                            const float* __restrict__ sc,
                                            const float* __restrict__ bi,
                                            float* __restrict__ outf) {
    int row = blockIdx.x;
    const float* r = in + (size_t)row * Dd;
    int t = threadIdx.x;
    float v0 = r[t], v1 = r[t + 256], v2 = r[t + 512];
    float s = v0 + v1 + v2;
    float q = v0 * v0 + v1 * v1 + v2 * v2;
    __shared__ float sh[16];
    float ws = warpsum(s), wq = warpsum(q);
    int w = t >> 5, l = t & 31;
    if (l == 0) { sh[w] = ws; sh[8 + w] = wq; }
    __syncthreads();
    float ssum = 0.f, ssq = 0.f;
    #pragma unroll
    for (int i = 0; i < 8; i++) { ssum += sh[i]; ssq += sh[8 + i]; }
    float mean = ssum * (1.0f / Dd);
    float var  = ssq * (1.0f / Dd) - mean * mean;
    float inv  = rsqrtf(var + EPS);
    #pragma unroll
    for (int kk = 0; kk < 3; kk++) {
        int c = t + kk * 256;
        float v = (kk == 0 ? v0 : (kk == 1 ? v1 : v2));
        float val = (v - mean) * inv * sc[c] + bi[c];
        if (ACT) val = val / (1.0f + expf(-val));
        size_t off = (size_t)row * Dd + c;
        if (WSPLIT) split2(val, g_ah[off], g_al[off]);
        if (FINAL) {
            float o = val + g_x2[off];
            float a = fabsf(o);
            outf[off] = a + log1pf(expf(-2.0f * a)) - 0.69314718055994530942f;
        }
    }
}

// ---------------- tensor-core GEMM: C = [g_ah,g_al] @ [Bh,Bl] (+bias) ----------------
// 2-stage cp.async pipeline. SPLITOUT: write bf16 split to Ch/Cl instead of f32.
template <int SPLITOUT>
__global__ __launch_bounds__(256) void gemm_bf16(const bf16* __restrict__ Bh,
                                                 const bf16* __restrict__ Bl,
                                                 const float* __restrict__ bias,
                                                 float* __restrict__ C,
                                                 bf16* __restrict__ Ch,
                                                 bf16* __restrict__ Cl,
                                                 int M, int N, int K) {
    extern __shared__ bf16 smem[];
    // As[st*2+hl][128][40], Bs[st*2+hl][32][136]
    bf16 (*As)[128][40] = reinterpret_cast<bf16 (*)[128][40]>(smem);
    bf16 (*Bs)[32][136] = reinterpret_cast<bf16 (*)[32][136]>(smem + 4 * 128 * 40);

    int tid = threadIdx.x;
    int wid = tid >> 5, lane = tid & 31;
    int wm = (wid & 3) * 32;
    int wn = (wid >> 2) * 64;
    int bm0 = blockIdx.y * 128;
    int bn0 = blockIdx.x * 128;

    float acc[16][4];
    #pragma unroll
    for (int i = 0; i < 16; i++)
        #pragma unroll
        for (int j = 0; j < 4; j++) acc[i][j] = 0.f;

    int mi = lane >> 3;
    int mr = lane & 7;

    // per-thread load coords
    int ar0 = tid >> 2,  aco = (tid & 3) * 8;           // A: chunk tid of 512 (2 per thread)
    int ar1 = (tid + 256) >> 2, aco1 = ((tid + 256) & 3) * 8;
    int br0 = tid >> 4,  bco = (tid & 15) * 8;
    int br1 = (tid + 256) >> 4, bco1 = ((tid + 256) & 15) * 8;

    auto load_stage = [&](int st, int kt) {
        cpa16(smem_u32(&As[st*2+0][ar0][aco]),  &g_ah[(size_t)(bm0 + ar0) * K + kt + aco]);
        cpa16(smem_u32(&As[st*2+0][ar1][aco1]), &g_ah[(size_t)(bm0 + ar1) * K + kt + aco1]);
        cpa16(smem_u32(&As[st*2+1][ar0][aco]),  &g_al[(size_t)(bm0 + ar0) * K + kt + aco]);
        cpa16(smem_u32(&As[st*2+1][ar1][aco1]), &g_al[(size_t)(bm0 + ar1) * K + kt + aco1]);
        cpa16(smem_u32(&Bs[st*2+0][br0][bco]),  &Bh[(size_t)(kt + br0) * N + bn0 + bco]);
        cpa16(smem_u32(&Bs[st*2+0][br1][bco1]), &Bh[(size_t)(kt + br1) * N + bn0 + bco1]);
        cpa16(smem_u32(&Bs[st*2+1][br0][bco]),  &Bl[(size_t)(kt + br0) * N + bn0 + bco]);
        cpa16(smem_u32(&Bs[st*2+1][br1][bco1]), &Bl[(size_t)(kt + br1) * N + bn0 + bco1]);
    };

    const int NT = Dd / 32;   // 24 k-tiles
    load_stage(0, 0);
    CP_COMMIT();

    for (int t = 0; t < NT; t++) {
        if (t + 1 < NT) {
            load_stage((t + 1) & 1, (t + 1) * 32);
            CP_COMMIT();
            CP_WAIT(1);
        } else {
            CP_WAIT(0);
        }
        __syncthreads();
        int st = t & 1;
        #pragma unroll
        for (int ks = 0; ks < 32; ks += 16) {
            u32 aH[2][4], aL[2][4];
            #pragma unroll
            for (int mt = 0; mt < 2; mt++) {
                int row = wm + mt * 16 + (mi & 1) * 8 + mr;
                int col = ks + (mi >> 1) * 8;
                ldm_x4(aH[mt], smem_u32(&As[st*2+0][row][col]));
                ldm_x4(aL[mt], smem_u32(&As[st*2+1][row][col]));
            }
            #pragma unroll
            for (int nt = 0; nt < 4; nt++) {
                u32 bH[4], bL[4];
                int brow = ks + (mi & 1) * 8 + mr;
                int bcol = wn + nt * 16 + (mi >> 1) * 8;
                ldm_x4_t(bH, smem_u32(&Bs[st*2+0][brow][bcol]));
                ldm_x4_t(bL, smem_u32(&Bs[st*2+1][brow][bcol]));
                #pragma unroll
                for (int mt = 0; mt < 2; mt++) {
                    #pragma unroll
                    for (int h2 = 0; h2 < 2; h2++) {
                        float* c = acc[mt * 8 + nt * 2 + h2];
                        mma_bf16(c, aH[mt], bH[h2 * 2], bH[h2 * 2 + 1]);
                        mma_bf16(c, aH[mt], bL[h2 * 2], bL[h2 * 2 + 1]);
                        mma_bf16(c, aL[mt], bH[h2 * 2], bH[h2 * 2 + 1]);
                    }
                }
            }
        }
        __syncthreads();
    }

    int qr = lane >> 2;
    int qc = (lane & 3) * 2;
    #pragma unroll
    for (int mt = 0; mt < 2; mt++) {
        #pragma unroll
        for (int nt = 0; nt < 8; nt++) {
            float* c = acc[mt * 8 + nt];
            int row = bm0 + wm + mt * 16 + qr;
            int col = bn0 + wn + nt * 8 + qc;
            if (SPLITOUT) {
                bf16 h0, l0, h1, l1;
                split2(c[0], h0, l0); split2(c[1], h1, l1);
                *(u32*)&Ch[(size_t)row * N + col] = pack_bf2(h0, h1);
                *(u32*)&Cl[(size_t)row * N + col] = pack_bf2(l0, l1);
                split2(c[2], h0, l0); split2(c[3], h1, l1);
                *(u32*)&Ch[(size_t)(row + 8) * N + col] = pack_bf2(h0, h1);
                *(u32*)&Cl[(size_t)(row + 8) * N + col] = pack_bf2(l0, l1);
            } else {
                float b0 = 0.f, b1 = 0.f;
                if (bias) { b0 = bias[col]; b1 = bias[col + 1]; }
                *(float2*)&C[(size_t)row * N + col] = make_float2(c[0] + b0, c[1] + b1);
                *(float2*)&C[(size_t)(row + 8) * N + col] = make_float2(c[2] + b0, c[3] + b1);
            }
        }
    }
}

// ---------------- circulant mix on tensor cores ----------------
// Y[i, k] = sum_j alpha[(i-j) mod N] * V[j, k]  per (b,h); out x2 = x + Y (f32 + split)
__global__ __launch_bounds__(256) void circ_k(const float* __restrict__ alpha,
                                              const float* __restrict__ x) {
    __shared__ bf16 Vs[2][2][64][72];        // [stage][hi/lo][k][n]
    __shared__ u32 qp_h[2][584], qp_l[2][584];  // [parity][pair index]

    int i0 = blockIdx.x * 128;
    int h  = blockIdx.y;
    int b  = blockIdx.z;
    int tid = threadIdx.x;
    int wid = tid >> 5, lane = tid & 31;
    int wm = wid * 16;                        // warp tile: 16 rows x 64 cols
    int mi = lane >> 3, mr = lane & 7;

    // fill alpha pair tables: q[t] = alpha[(i0 + 127 - t) & 1023], t in [0, 1152)
    const float* arow = alpha + h * Nn;
    for (int s = tid; s < 576; s += 256) {
        #pragma unroll
        for (int p = 0; p < 2; p++) {
            int t0 = 2 * s + p;
            float a0 = arow[(i0 + 127 - t0) & (Nn - 1)];
            float a1 = arow[(i0 + 126 - t0) & (Nn - 1)];
            bf16 h0, l0, h1, l1;
            split2(a0, h0, l0); split2(a1, h1, l1);
            qp_h[p][s] = pack_bf2(h0, h1);
            qp_l[p][s] = pack_bf2(l0, l1);
        }
    }

    // V tile loads (cp.async): 1024 16B-chunks per stage, 4 per thread
    auto loadV = [&](int st, int j0) {
        #pragma unroll
        for (int i = 0; i < 4; i++) {
            int c = tid + i * 256;
            int arr = c >> 9;           // 0 = hi, 1 = lo
            int cc = c & 511;
            int r = cc >> 3, co = (cc & 7) * 8;
            const bf16* src = (arr ? g_vl : g_vh) +
                              (size_t)(b * Nn + j0 + r) * Dd + h * HS + co;
            cpa16(smem_u32(&Vs[st][arr][r][co]), src);
        }
    };

    loadV(0, 0);
    CP_COMMIT();

    float acc[8][4];
    #pragma unroll
    for (int i = 0; i < 8; i++)
        #pragma unroll
        for (int j = 0; j < 4; j++) acc[i][j] = 0.f;

    int li0 = wm + (lane >> 2);
    int p   = (127 - li0) & 1;
    int sb  = (127 - li0 - p) >> 1;           // s = sb + j/2  (j even)
    const u32* qh = qp_h[p];
    const u32* ql = qp_l[p];

    __syncthreads();   // qp tables ready

    for (int t = 0; t < 16; t++) {
        if (t + 1 < 16) {
            loadV((t + 1) & 1, (t + 1) * 64);
            CP_COMMIT();
            CP_WAIT(1);
        } else {
            CP_WAIT(0);
        }
        __syncthreads();
        int st = t & 1;
        #pragma unroll
        for (int kc = 0; kc < 4; kc++) {
            int j = t * 64 + kc * 16;
            int s0 = sb + (j >> 1) + (lane & 3);
            // Toeplitz: a3 == a0
            u32 aH[4], aL[4];
            aH[0] = qh[s0];     aL[0] = ql[s0];
            aH[1] = qh[s0 - 4]; aL[1] = ql[s0 - 4];
            aH[2] = qh[s0 + 4]; aL[2] = ql[s0 + 4];
            aH[3] = aH[0];      aL[3] = aL[0];
            #pragma unroll
            for (int n2 = 0; n2 < 4; n2++) {
                u32 bH[4], bL[4];
                int brow = kc * 16 + (mi & 1) * 8 + mr;
                int bcol = n2 * 16 + (mi >> 1) * 8;
                ldm_x4_t(bH, smem_u32(&Vs[st][0][brow][bcol]));
                ldm_x4_t(bL, smem_u32(&Vs[st][1][brow][bcol]));
                #pragma unroll
                for (int h2 = 0; h2 < 2; h2++) {
                    float* c = acc[n2 * 2 + h2];
                    mma_bf16(c, aH, bH[h2 * 2], bH[h2 * 2 + 1]);
                    mma_bf16(c, aH, bL[h2 * 2], bL[h2 * 2 + 1]);
                    mma_bf16(c, aL, bH[h2 * 2], bH[h2 * 2 + 1]);
                }
            }
        }
        __syncthreads();
    }

    // epilogue: residual add, f32 store + split store
    int qr = lane >> 2;
    int qc = (lane & 3) * 2;
    #pragma unroll
    for (int nt = 0; nt < 8; nt++) {
        float* c = acc[nt];
        #pragma unroll
        for (int half = 0; half < 2; half++) {
            int row = b * Nn + i0 + wm + qr + half * 8;
            int col = h * HS + nt * 8 + qc;
            size_t off = (size_t)row * Dd + col;
            float2 xv = *(const float2*)&x[off];
            float o0 = c[half * 2 + 0] + xv.x;
            float o1 = c[half * 2 + 1] + xv.y;
            *(float2*)&g_x2[off] = make_float2(o0, o1);
            bf16 h0, l0, h1, l1;
            split2(o0, h0, l0); split2(o1, h1, l1);
            *(u32*)&g_ah[off] = pack_bf2(h0, h1);
            *(u32*)&g_al[off] = pack_bf2(l0, l1);
        }
    }
}

extern "C" void kernel_launch(void* const* d_in, const int* in_sizes, int n_in,
                              void* d_out, int out_size) {
    const float* x         = (const float*)d_in[0];
    const float* ln1_scale = (const float*)d_in[1];
    const float* ln1_bias  = (const float*)d_in[2];
    const float* Wv        = (const float*)d_in[3];
    const float* alpha     = (const float*)d_in[4];
    const float* Wf        = (const float*)d_in[5];
    const float* bf        = (const float*)d_in[6];
    const float* lnf_scale = (const float*)d_in[7];
    const float* lnf_bias  = (const float*)d_in[8];
    float* out = (float*)d_out;

    float *t;
    bf16 *wh, *wl, *vh, *vl;
    cudaGetSymbolAddress((void**)&t,  g_t);
    cudaGetSymbolAddress((void**)&wh, g_wh);
    cudaGetSymbolAddress((void**)&wl, g_wl);
    cudaGetSymbolAddress((void**)&vh, g_vh);
    cudaGetSymbolAddress((void**)&vl, g_vl);

    const int GSMEM = (4 * 128 * 40 + 4 * 32 * 136) * (int)sizeof(bf16);  // 75776
    static int smem_set = 0;
    if (!smem_set) {
        cudaFuncSetAttribute(gemm_bf16<0>, cudaFuncAttributeMaxDynamicSharedMemorySize, GSMEM);
        cudaFuncSetAttribute(gemm_bf16<1>, cudaFuncAttributeMaxDynamicSharedMemorySize, GSMEM);
        smem_set = 1;
    }

    dim3 ggrid(Dd / 128, ROWS / 128);

    wsplit_wv_k<<<(D2 + 255) / 256, 256>>>(Wv);
    wsplit_wf_k<<<(2 * D2 + 255) / 256, 256>>>(Wf);
    // xn = LN(x) -> split
    ln_k<0, 1, 0><<<ROWS, 256>>>(x, ln1_scale, ln1_bias, nullptr);
    // v = xn @ Wcat -> split (vh, vl)
    gemm_bf16<1><<<ggrid, 256, GSMEM>>>(wh, wl, nullptr, nullptr, vh, vl, ROWS, Dd, Dd);
    // x2 = x + circ(alpha, v)  -> f32 + split
    circ_k<<<dim3(Nn / 128, Hh, Bb), 256>>>(alpha, x);
    // FFN0: t = x2 @ Wf0 + bf0
    gemm_bf16<0><<<ggrid, 256, GSMEM>>>(wh + D2, wl + D2, bf, t, nullptr, nullptr, ROWS, Dd, Dd);
    // z0 = swish(LN(t)) -> split
    ln_k<1, 1, 0><<<ROWS, 256>>>(t, lnf_scale, lnf_bias, nullptr);
    // FFN1: t = z0 @ Wf1 + bf1
    gemm_bf16<0><<<ggrid, 256, GSMEM>>>(wh + 2 * D2, wl + 2 * D2, bf + Dd, t, nullptr, nullptr, ROWS, Dd, Dd);
    // z1 = swish(LN(t)); out = log_cosh(z1 + x2)
    ln_k<1, 0, 1><<<ROWS, 256>>>(t, lnf_scale + Dd, lnf_bias + Dd, out);
}

// round 11
// speedup vs baseline: 2.5427x; 1.0755x over previous
#include <cuda_runtime.h>
#include <cuda_bf16.h>
#include <math.h>

#define Bb 16
#define Nn 1024
#define Dd 768
#define Hh 12
#define HS 64
#define ROWS (Bb*Nn)          // 16384
#define TOT  (Bb*Nn*Dd)       // 12,582,912
#define D2   (Dd*Dd)
#define EPS  1e-6f

typedef unsigned long long u64;
typedef unsigned int u32;
typedef __nv_bfloat16 bf16;

// scratch (no allocations allowed)
__device__ float g_x2[TOT];
__device__ float g_t[TOT];
__device__ bf16 g_vh[TOT];                // v split hi
__device__ bf16 g_vl[TOT];                // v split lo
__device__ bf16 g_ah[TOT];                // activation split hi (xn -> x2 -> z0)
__device__ bf16 g_al[TOT];                // activation split lo
__device__ bf16 g_wh[3*D2];               // weights hi (row-major [k][n]): [wcat, wf0, wf1]
__device__ bf16 g_wl[3*D2];

// ---------------- helpers ----------------
__device__ __forceinline__ void split2(float x, bf16& h, bf16& l) {
    h = __float2bfloat16(x);
    l = __float2bfloat16(x - __bfloat162float(h));
}
__device__ __forceinline__ u32 pack_bf2(bf16 a, bf16 b) {
    __nv_bfloat162 p; p.x = a; p.y = b;
    return *reinterpret_cast<u32*>(&p);
}
__device__ __forceinline__ u32 smem_u32(const void* p) {
    return (u32)__cvta_generic_to_shared(p);
}
__device__ __forceinline__ void cpa16(u32 dst, const void* src) {
    asm volatile("cp.async.cg.shared.global [%0], [%1], 16;" :: "r"(dst), "l"(src));
}
#define CP_COMMIT() asm volatile("cp.async.commit_group;")
#define CP_WAIT(n)  asm volatile("cp.async.wait_group %0;" :: "n"(n))

__device__ __forceinline__ void ldm_x4(u32 r[4], u32 addr) {
    asm volatile("ldmatrix.sync.aligned.m8n8.x4.shared.b16 {%0,%1,%2,%3}, [%4];"
                 : "=r"(r[0]), "=r"(r[1]), "=r"(r[2]), "=r"(r[3]) : "r"(addr));
}
__device__ __forceinline__ void ldm_x4_t(u32 r[4], u32 addr) {
    asm volatile("ldmatrix.sync.aligned.m8n8.x4.trans.shared.b16 {%0,%1,%2,%3}, [%4];"
                 : "=r"(r[0]), "=r"(r[1]), "=r"(r[2]), "=r"(r[3]) : "r"(addr));
}
__device__ __forceinline__ void mma_bf16(float c[4], const u32 a[4], u32 b0, u32 b1) {
    asm volatile("mma.sync.aligned.m16n8k16.row.col.f32.bf16.bf16.f32 "
                 "{%0,%1,%2,%3}, {%4,%5,%6,%7}, {%8,%9}, {%0,%1,%2,%3};"
                 : "+f"(c[0]), "+f"(c[1]), "+f"(c[2]), "+f"(c[3])
                 : "r"(a[0]), "r"(a[1]), "r"(a[2]), "r"(a[3]), "r"(b0), "r"(b1));
}

// ---------------- weight prep ----------------
__global__ void wsplit_wv_k(const float* __restrict__ Wv) {
    int idx = blockIdx.x * 256 + threadIdx.x;
    if (idx >= D2) return;
    int col = idx % Dd;            // h*HS + k
    int d   = idx / Dd;
    int h = col / HS, k = col % HS;
    float v = Wv[((size_t)h * Dd + d) * HS + k];
    split2(v, g_wh[idx], g_wl[idx]);
}
__global__ void wsplit_wf_k(const float* __restrict__ Wf) {
    int idx = blockIdx.x * 256 + threadIdx.x;
    if (idx >= 2 * D2) return;
    split2(Wf[idx], g_wh[D2 + idx], g_wl[D2 + idx]);
}

// ---------------- layernorm (+swish) ----------------
__inline__ __device__ float warpsum(float v) {
    #pragma unroll
    for (int o = 16; o; o >>= 1) v += __shfl_xor_sync(0xffffffffu, v, o);
    return v;
}

// WSPLIT: write split to g_ah/g_al.  FINAL: out = log_cosh(val + x2)
template <int ACT, int WSPLIT, int FINAL>
__global__ __launch_bounds__(256) void ln_k(const float* __restrict__ in,
                                            const float* __restrict__ sc,
                                            const float* __restrict__ bi,
                                            float* __restrict__ outf) {
    int row = blockIdx.x;
    const float* r = in + (size_t)row * Dd;
    int t = threadIdx.x;
    float v0 = r[t], v1 = r[t + 256], v2 = r[t + 512];
    float s = v0 + v1 + v2;
    float q = v0 * v0 + v1 * v1 + v2 * v2;
    __shared__ float sh[16];
    float ws = warpsum(s), wq = warpsum(q);
    int w = t >> 5, l = t & 31;
    if (l == 0) { sh[w] = ws; sh[8 + w] = wq; }
    __syncthreads();
    float ssum = 0.f, ssq = 0.f;
    #pragma unroll
    for (int i = 0; i < 8; i++) { ssum += sh[i]; ssq += sh[8 + i]; }
    float mean = ssum * (1.0f / Dd);
    float var  = ssq * (1.0f / Dd) - mean * mean;
    float inv  = rsqrtf(var + EPS);
    #pragma unroll
    for (int kk = 0; kk < 3; kk++) {
        int c = t + kk * 256;
        float v = (kk == 0 ? v0 : (kk == 1 ? v1 : v2));
        float val = (v - mean) * inv * sc[c] + bi[c];
        if (ACT) val = val / (1.0f + expf(-val));
        size_t off = (size_t)row * Dd + c;
        if (WSPLIT) split2(val, g_ah[off], g_al[off]);
        if (FINAL) {
            float o = val + g_x2[off];
            float a = fabsf(o);
            outf[off] = a + log1pf(expf(-2.0f * a)) - 0.69314718055994530942f;
        }
    }
}

// ---------------- tensor-core GEMM (mma.sync), 3-stage pipeline ----------------
// C = [g_ah,g_al] @ [Bh,Bl] (+bias); B row-major [K,N].
// Row paddings MUST keep 16B alignment: 40 hw = 80 B, 136 hw = 272 B.
#define AS_ROW 40
#define BS_ROW 136
#define A_STG (2*128*AS_ROW)     // 10240 hw
#define B_STG (2*32*BS_ROW)      // 8704 hw
#define GSMEM_HW (3*A_STG + 3*B_STG)   // 56832 hw = 113664 B

template <int SPLITOUT>
__global__ __launch_bounds__(256) void gemm_bf16(const bf16* __restrict__ Bh,
                                                 const bf16* __restrict__ Bl,
                                                 const float* __restrict__ bias,
                                                 float* __restrict__ C,
                                                 bf16* __restrict__ Ch,
                                                 bf16* __restrict__ Cl,
                                                 int M, int N, int K) {
    extern __shared__ bf16 smem[];
    bf16* Abase = smem;
    bf16* Bbase = smem + 3 * A_STG;

    int tid = threadIdx.x;
    int wid = tid >> 5, lane = tid & 31;
    int wm = (wid & 3) * 32;
    int wn = (wid >> 2) * 64;
    int bm0 = blockIdx.y * 128;
    int bn0 = blockIdx.x * 128;

    float acc[16][4];
    #pragma unroll
    for (int i = 0; i < 16; i++)
        #pragma unroll
        for (int j = 0; j < 4; j++) acc[i][j] = 0.f;

    int mi = lane >> 3;
    int mr = lane & 7;

    auto load_stage = [&](int st, int kt) {
        bf16* As = Abase + st * A_STG;
        bf16* Bs = Bbase + st * B_STG;
        #pragma unroll
        for (int i = 0; i < 4; i++) {
            int c = tid + i * 256;           // 0..1023
            int hl = c >> 9, cc = c & 511;
            {   // A chunk: row = cc>>2, col = (cc&3)*8
                int row = cc >> 2, col = (cc & 3) * 8;
                const bf16* src = (hl ? g_al : g_ah) + (size_t)(bm0 + row) * K + kt + col;
                cpa16(smem_u32(As + hl * 128 * AS_ROW + row * AS_ROW + col), src);
            }
            {   // B chunk: row = cc>>4, col = (cc&15)*8
                int row = cc >> 4, col = (cc & 15) * 8;
                const bf16* src = (hl ? Bl : Bh) + (size_t)(kt + row) * N + bn0 + col;
                cpa16(smem_u32(Bs + hl * 32 * BS_ROW + row * BS_ROW + col), src);
            }
        }
    };

    const int NT = Dd / 32;   // 24 k-tiles
    load_stage(0, 0);  CP_COMMIT();
    load_stage(1, 32); CP_COMMIT();

    for (int t = 0; t < NT; t++) {
        if (t + 1 < NT) { CP_WAIT(1); } else { CP_WAIT(0); }
        __syncthreads();                       // stage t resident; compute(t-1) done everywhere
        if (t + 2 < NT) {                      // overwrites stage (t-1)%3 — safe after barrier
            load_stage((t + 2) % 3, (t + 2) * 32);
            CP_COMMIT();
        }
        int st = t % 3;
        bf16* As = Abase + st * A_STG;
        bf16* Bs = Bbase + st * B_STG;
        #pragma unroll
        for (int ks = 0; ks < 32; ks += 16) {
            u32 aH[2][4], aL[2][4];
            #pragma unroll
            for (int mt = 0; mt < 2; mt++) {
                int row = wm + mt * 16 + (mi & 1) * 8 + mr;
                int col = ks + (mi >> 1) * 8;
                ldm_x4(aH[mt], smem_u32(As + 0 * 128 * AS_ROW + row * AS_ROW + col));
                ldm_x4(aL[mt], smem_u32(As + 1 * 128 * AS_ROW + row * AS_ROW + col));
            }
            #pragma unroll
            for (int nt = 0; nt < 4; nt++) {
                u32 bH[4], bL[4];
                int brow = ks + (mi & 1) * 8 + mr;
                int bcol = wn + nt * 16 + (mi >> 1) * 8;
                ldm_x4_t(bH, smem_u32(Bs + 0 * 32 * BS_ROW + brow * BS_ROW + bcol));
                ldm_x4_t(bL, smem_u32(Bs + 1 * 32 * BS_ROW + brow * BS_ROW + bcol));
                #pragma unroll
                for (int mt = 0; mt < 2; mt++) {
                    #pragma unroll
                    for (int h2 = 0; h2 < 2; h2++) {
                        float* c = acc[mt * 8 + nt * 2 + h2];
                        mma_bf16(c, aH[mt], bH[h2 * 2], bH[h2 * 2 + 1]);
                        mma_bf16(c, aH[mt], bL[h2 * 2], bL[h2 * 2 + 1]);
                        mma_bf16(c, aL[mt], bH[h2 * 2], bH[h2 * 2 + 1]);
                    }
                }
            }
        }
    }

    int qr = lane >> 2;
    int qc = (lane & 3) * 2;
    #pragma unroll
    for (int mt = 0; mt < 2; mt++) {
        #pragma unroll
        for (int nt = 0; nt < 8; nt++) {
            float* c = acc[mt * 8 + nt];
            int row = bm0 + wm + mt * 16 + qr;
            int col = bn0 + wn + nt * 8 + qc;
            if (SPLITOUT) {
                bf16 h0, l0, h1, l1;
                split2(c[0], h0, l0); split2(c[1], h1, l1);
                *(u32*)&Ch[(size_t)row * N + col] = pack_bf2(h0, h1);
                *(u32*)&Cl[(size_t)row * N + col] = pack_bf2(l0, l1);
                split2(c[2], h0, l0); split2(c[3], h1, l1);
                *(u32*)&Ch[(size_t)(row + 8) * N + col] = pack_bf2(h0, h1);
                *(u32*)&Cl[(size_t)(row + 8) * N + col] = pack_bf2(l0, l1);
            } else {
                float b0 = 0.f, b1 = 0.f;
                if (bias) { b0 = bias[col]; b1 = bias[col + 1]; }
                *(float2*)&C[(size_t)row * N + col] = make_float2(c[0] + b0, c[1] + b1);
                *(float2*)&C[(size_t)(row + 8) * N + col] = make_float2(c[2] + b0, c[3] + b1);
            }
        }
    }
}

// ---------------- circulant mix (mma.sync), 3-stage pipeline ----------------
// Y[i,k] = sum_j alpha[(i-j) mod N] * V[j,k] per (b,h); x2 = x + Y (f32 + split)
#define VS_ROW 72                // 144 B, 16B-aligned
#define V_STG (2*64*VS_ROW)      // 9216 hw per stage
#define CSMEM_HW (3*V_STG)       // 27648 hw = 55296 B

__global__ __launch_bounds__(256) void circ_k(const float* __restrict__ alpha,
                                              const float* __restrict__ x) {
    extern __shared__ bf16 vsmem[];
    __shared__ u32 qp_h[2][584], qp_l[2][584];

    int i0 = blockIdx.x * 128;
    int h  = blockIdx.y;
    int b  = blockIdx.z;
    int tid = threadIdx.x;
    int wid = tid >> 5, lane = tid & 31;
    int wm = wid * 16;
    int mi = lane >> 3, mr = lane & 7;

    const float* arow = alpha + h * Nn;
    for (int s = tid; s < 576; s += 256) {
        #pragma unroll
        for (int p = 0; p < 2; p++) {
            int t0 = 2 * s + p;
            float a0 = arow[(i0 + 127 - t0) & (Nn - 1)];
            float a1 = arow[(i0 + 126 - t0) & (Nn - 1)];
            bf16 h0, l0, h1, l1;
            split2(a0, h0, l0); split2(a1, h1, l1);
            qp_h[p][s] = pack_bf2(h0, h1);
            qp_l[p][s] = pack_bf2(l0, l1);
        }
    }

    auto loadV = [&](int st, int j0) {
        bf16* Vs = vsmem + st * V_STG;
        #pragma unroll
        for (int i = 0; i < 4; i++) {
            int c = tid + i * 256;
            int arr = c >> 9;
            int cc = c & 511;
            int r = cc >> 3, co = (cc & 7) * 8;
            const bf16* src = (arr ? g_vl : g_vh) +
                              (size_t)(b * Nn + j0 + r) * Dd + h * HS + co;
            cpa16(smem_u32(Vs + arr * 64 * VS_ROW + r * VS_ROW + co), src);
        }
    };

    loadV(0, 0);  CP_COMMIT();
    loadV(1, 64); CP_COMMIT();

    float acc[8][4];
    #pragma unroll
    for (int i = 0; i < 8; i++)
        #pragma unroll
        for (int j = 0; j < 4; j++) acc[i][j] = 0.f;

    int li0 = wm + (lane >> 2);
    int p   = (127 - li0) & 1;
    int sb  = (127 - li0 - p) >> 1;
    const u32* qh = qp_h[p];
    const u32* ql = qp_l[p];

    for (int t = 0; t < 16; t++) {
        if (t + 1 < 16) { CP_WAIT(1); } else { CP_WAIT(0); }
        __syncthreads();                       // also publishes qp tables at t=0
        if (t + 2 < 16) {
            loadV((t + 2) % 3, (t + 2) * 64);
            CP_COMMIT();
        }
        bf16* Vs = vsmem + (t % 3) * V_STG;
        #pragma unroll
        for (int kc = 0; kc < 4; kc++) {
            int j = t * 64 + kc * 16;
            int s0 = sb + (j >> 1) + (lane & 3);
            u32 aH[4], aL[4];
            aH[0] = qh[s0];     aL[0] = ql[s0];
            aH[1] = qh[s0 - 4]; aL[1] = ql[s0 - 4];
            aH[2] = qh[s0 + 4]; aL[2] = ql[s0 + 4];
            aH[3] = aH[0];      aL[3] = aL[0];
            #pragma unroll
            for (int n2 = 0; n2 < 4; n2++) {
                u32 bH[4], bL[4];
                int brow = kc * 16 + (mi & 1) * 8 + mr;
                int bcol = n2 * 16 + (mi >> 1) * 8;
                ldm_x4_t(bH, smem_u32(Vs + 0 * 64 * VS_ROW + brow * VS_ROW + bcol));
                ldm_x4_t(bL, smem_u32(Vs + 1 * 64 * VS_ROW + brow * VS_ROW + bcol));
                #pragma unroll
                for (int h2 = 0; h2 < 2; h2++) {
                    float* c = acc[n2 * 2 + h2];
                    mma_bf16(c, aH, bH[h2 * 2], bH[h2 * 2 + 1]);
                    mma_bf16(c, aH, bL[h2 * 2], bL[h2 * 2 + 1]);
                    mma_bf16(c, aL, bH[h2 * 2], bH[h2 * 2 + 1]);
                }
            }
        }
    }

    int qr = lane >> 2;
    int qc = (lane & 3) * 2;
    #pragma unroll
    for (int nt = 0; nt < 8; nt++) {
        float* c = acc[nt];
        #pragma unroll
        for (int half = 0; half < 2; half++) {
            int row = b * Nn + i0 + wm + qr + half * 8;
            int col = h * HS + nt * 8 + qc;
            size_t off = (size_t)row * Dd + col;
            float2 xv = *(const float2*)&x[off];
            float o0 = c[half * 2 + 0] + xv.x;
            float o1 = c[half * 2 + 1] + xv.y;
            *(float2*)&g_x2[off] = make_float2(o0, o1);
            bf16 h0, l0, h1, l1;
            split2(o0, h0, l0); split2(o1, h1, l1);
            *(u32*)&g_ah[off] = pack_bf2(h0, h1);
            *(u32*)&g_al[off] = pack_bf2(l0, l1);
        }
    }
}

extern "C" void kernel_launch(void* const* d_in, const int* in_sizes, int n_in,
                              void* d_out, int out_size) {
    const float* x         = (const float*)d_in[0];
    const float* ln1_scale = (const float*)d_in[1];
    const float* ln1_bias  = (const float*)d_in[2];
    const float* Wv        = (const float*)d_in[3];
    const float* alpha     = (const float*)d_in[4];
    const float* Wf        = (const float*)d_in[5];
    const float* bf        = (const float*)d_in[6];
    const float* lnf_scale = (const float*)d_in[7];
    const float* lnf_bias  = (const float*)d_in[8];
    float* out = (float*)d_out;

    float *t;
    bf16 *wh, *wl, *vh, *vl;
    cudaGetSymbolAddress((void**)&t,  g_t);
    cudaGetSymbolAddress((void**)&wh, g_wh);
    cudaGetSymbolAddress((void**)&wl, g_wl);
    cudaGetSymbolAddress((void**)&vh, g_vh);
    cudaGetSymbolAddress((void**)&vl, g_vl);

    const int GSMEM = GSMEM_HW * (int)sizeof(bf16);   // 113664
    const int CSMEM = CSMEM_HW * (int)sizeof(bf16);   // 55296
    cudaFuncSetAttribute(gemm_bf16<0>, cudaFuncAttributeMaxDynamicSharedMemorySize, GSMEM);
    cudaFuncSetAttribute(gemm_bf16<1>, cudaFuncAttributeMaxDynamicSharedMemorySize, GSMEM);
    cudaFuncSetAttribute(circ_k, cudaFuncAttributeMaxDynamicSharedMemorySize, CSMEM);

    dim3 ggrid(Dd / 128, ROWS / 128);

    wsplit_wv_k<<<(D2 + 255) / 256, 256>>>(Wv);
    wsplit_wf_k<<<(2 * D2 + 255) / 256, 256>>>(Wf);
    // xn = LN(x) -> split
    ln_k<0, 1, 0><<<ROWS, 256>>>(x, ln1_scale, ln1_bias, nullptr);
    // v = xn @ Wcat -> split (vh, vl)
    gemm_bf16<1><<<ggrid, 256, GSMEM>>>(wh, wl, nullptr, nullptr, vh, vl, ROWS, Dd, Dd);
    // x2 = x + circ(alpha, v)  -> f32 + split
    circ_k<<<dim3(Nn / 128, Hh, Bb), 256, CSMEM>>>(alpha, x);
    // FFN0: t = x2 @ Wf0 + bf0
    gemm_bf16<0><<<ggrid, 256, GSMEM>>>(wh + D2, wl + D2, bf, t, nullptr, nullptr, ROWS, Dd, Dd);
    // z0 = swish(LN(t)) -> split
    ln_k<1, 1, 0><<<ROWS, 256>>>(t, lnf_scale, lnf_bias, nullptr);
    // FFN1: t = z0 @ Wf1 + bf1
    gemm_bf16<0><<<ggrid, 256, GSMEM>>>(wh + 2 * D2, wl + 2 * D2, bf + Dd, t, nullptr, nullptr, ROWS, Dd, Dd);
    // z1 = swish(LN(t)); out = log_cosh(z1 + x2)
    ln_k<1, 0, 1><<<ROWS, 256>>>(t, lnf_scale + Dd, lnf_bias + Dd, out);
}

// round 13
// speedup vs baseline: 3.4346x; 1.3508x over previous
#include <cuda_runtime.h>
#include <cuda_fp16.h>
#include <math.h>

#define Bb 16
#define Nn 1024
#define Dd 768
#define Hh 12
#define HS 64
#define ROWS (Bb*Nn)          // 16384
#define TOT  (Bb*Nn*Dd)       // 12,582,912
#define D2   (Dd*Dd)
#define EPS  1e-6f

typedef unsigned long long u64;
typedef unsigned int u32;
typedef __half h16;

// scratch (no allocations allowed)
__device__ float g_x2[TOT];
__device__ float g_t[TOT];
__device__ h16 g_v[TOT];                  // v single fp16
__device__ h16 g_ah[TOT];                 // activation split hi (xn -> x2 -> z0)
__device__ h16 g_al[TOT];                 // activation split lo
__device__ h16 g_wh[3*D2];                // weights single fp16 [k][n]: [wcat, wf0, wf1]

// ---------------- helpers ----------------
__device__ __forceinline__ void split2h(float x, h16& h, h16& l) {
    h = __float2half_rn(x);
    l = __float2half_rn(x - __half2float(h));
}
__device__ __forceinline__ u32 pack_h2(h16 a, h16 b) {
    __half2 p; p.x = a; p.y = b;
    return *reinterpret_cast<u32*>(&p);
}
__device__ __forceinline__ u32 smem_u32(const void* p) {
    return (u32)__cvta_generic_to_shared(p);
}
__device__ __forceinline__ void cpa16(u32 dst, const void* src) {
    asm volatile("cp.async.cg.shared.global [%0], [%1], 16;" :: "r"(dst), "l"(src));
}
#define CP_COMMIT() asm volatile("cp.async.commit_group;")
#define CP_WAIT(n)  asm volatile("cp.async.wait_group %0;" :: "n"(n))

__device__ __forceinline__ void ldm_x4(u32 r[4], u32 addr) {
    asm volatile("ldmatrix.sync.aligned.m8n8.x4.shared.b16 {%0,%1,%2,%3}, [%4];"
                 : "=r"(r[0]), "=r"(r[1]), "=r"(r[2]), "=r"(r[3]) : "r"(addr));
}
__device__ __forceinline__ void ldm_x4_t(u32 r[4], u32 addr) {
    asm volatile("ldmatrix.sync.aligned.m8n8.x4.trans.shared.b16 {%0,%1,%2,%3}, [%4];"
                 : "=r"(r[0]), "=r"(r[1]), "=r"(r[2]), "=r"(r[3]) : "r"(addr));
}
__device__ __forceinline__ void mma_f16(float c[4], const u32 a[4], u32 b0, u32 b1) {
    asm volatile("mma.sync.aligned.m16n8k16.row.col.f32.f16.f16.f32 "
                 "{%0,%1,%2,%3}, {%4,%5,%6,%7}, {%8,%9}, {%0,%1,%2,%3};"
                 : "+f"(c[0]), "+f"(c[1]), "+f"(c[2]), "+f"(c[3])
                 : "r"(a[0]), "r"(a[1]), "r"(a[2]), "r"(a[3]), "r"(b0), "r"(b1));
}

// ---------------- weight prep (single fp16) ----------------
__global__ void wsplit_wv_k(const float* __restrict__ Wv) {
    int idx = blockIdx.x * 256 + threadIdx.x;
    if (idx >= D2) return;
    int col = idx % Dd;            // h*HS + k
    int d   = idx / Dd;
    int h = col / HS, k = col % HS;
    g_wh[idx] = __float2half_rn(Wv[((size_t)h * Dd + d) * HS + k]);
}
__global__ void wsplit_wf_k(const float* __restrict__ Wf) {
    int idx = blockIdx.x * 256 + threadIdx.x;
    if (idx >= 2 * D2) return;
    g_wh[D2 + idx] = __float2half_rn(Wf[idx]);
}

// ---------------- layernorm (+swish) ----------------
__inline__ __device__ float warpsum(float v) {
    #pragma unroll
    for (int o = 16; o; o >>= 1) v += __shfl_xor_sync(0xffffffffu, v, o);
    return v;
}

// WSPLIT: write split to g_ah/g_al.  FINAL: out = log_cosh(val + x2)
template <int ACT, int WSPLIT, int FINAL>
__global__ __launch_bounds__(256) void ln_k(const float* __restrict__ in,
                                            const float* __restrict__ sc,
                                            const float* __restrict__ bi,
                                            float* __restrict__ outf) {
    int row = blockIdx.x;
    const float* r = in + (size_t)row * Dd;
    int t = threadIdx.x;
    float v0 = r[t], v1 = r[t + 256], v2 = r[t + 512];
    float s = v0 + v1 + v2;
    float q = v0 * v0 + v1 * v1 + v2 * v2;
    __shared__ float sh[16];
    float ws = warpsum(s), wq = warpsum(q);
    int w = t >> 5, l = t & 31;
    if (l == 0) { sh[w] = ws; sh[8 + w] = wq; }
    __syncthreads();
    float ssum = 0.f, ssq = 0.f;
    #pragma unroll
    for (int i = 0; i < 8; i++) { ssum += sh[i]; ssq += sh[8 + i]; }
    float mean = ssum * (1.0f / Dd);
    float var  = ssq * (1.0f / Dd) - mean * mean;
    float inv  = rsqrtf(var + EPS);
    #pragma unroll
    for (int kk = 0; kk < 3; kk++) {
        int c = t + kk * 256;
        float v = (kk == 0 ? v0 : (kk == 1 ? v1 : v2));
        float val = (v - mean) * inv * sc[c] + bi[c];
        if (ACT) val = val / (1.0f + expf(-val));
        size_t off = (size_t)row * Dd + c;
        if (WSPLIT) split2h(val, g_ah[off], g_al[off]);
        if (FINAL) {
            float o = val + g_x2[off];
            float a = fabsf(o);
            outf[off] = a + log1pf(expf(-2.0f * a)) - 0.69314718055994530942f;
        }
    }
}

// ---------------- tensor-core GEMM (mma.sync fp16 2-term), 3-stage pipeline ----------------
// C = (Ah+Al) @ Bh (+bias); A split fp16 in g_ah/g_al, B single fp16 row-major [K,N].
#define AS_ROW 40                 // 80 B rows, 16B-aligned, conflict-free
#define BS_ROW 136                // 272 B rows
#define A_STG (2*128*AS_ROW)      // 10240 hw
#define B_STG (32*BS_ROW)         // 4352 hw
#define GSMEM_HW (3*(A_STG + B_STG))   // 43776 hw = 87552 B

template <int SPLITOUT>
__global__ __launch_bounds__(256) void gemm_f16(const h16* __restrict__ Bh,
                                                const float* __restrict__ bias,
                                                float* __restrict__ C,
                                                h16* __restrict__ Cv,
                                                int M, int N, int K) {
    extern __shared__ h16 smem[];
    h16* Abase = smem;
    h16* Bbase = smem + 3 * A_STG;

    int tid = threadIdx.x;
    int wid = tid >> 5, lane = tid & 31;
    int wm = (wid & 3) * 32;
    int wn = (wid >> 2) * 64;
    int bm0 = blockIdx.y * 128;
    int bn0 = blockIdx.x * 128;

    float acc[16][4];
    #pragma unroll
    for (int i = 0; i < 16; i++)
        #pragma unroll
        for (int j = 0; j < 4; j++) acc[i][j] = 0.f;

    int mi = lane >> 3;
    int mr = lane & 7;

    auto load_stage = [&](int st, int kt) {
        h16* As = Abase + st * A_STG;
        h16* Bs = Bbase + st * B_STG;
        #pragma unroll
        for (int i = 0; i < 4; i++) {        // A: 1024 chunks
            int c = tid + i * 256;
            int hl = c >> 9, cc = c & 511;
            int row = cc >> 2, col = (cc & 3) * 8;
            const h16* src = (hl ? g_al : g_ah) + (size_t)(bm0 + row) * K + kt + col;
            cpa16(smem_u32(As + hl * 128 * AS_ROW + row * AS_ROW + col), src);
        }
        #pragma unroll
        for (int i = 0; i < 2; i++) {        // B: 512 chunks
            int c = tid + i * 256;
            int row = c >> 4, col = (c & 15) * 8;
            const h16* src = Bh + (size_t)(kt + row) * N + bn0 + col;
            cpa16(smem_u32(Bs + row * BS_ROW + col), src);
        }
    };

    const int NT = Dd / 32;   // 24 k-tiles
    load_stage(0, 0);  CP_COMMIT();
    load_stage(1, 32); CP_COMMIT();

    for (int t = 0; t < NT; t++) {
        if (t + 1 < NT) { CP_WAIT(1); } else { CP_WAIT(0); }
        __syncthreads();
        if (t + 2 < NT) {
            load_stage((t + 2) % 3, (t + 2) * 32);
            CP_COMMIT();
        }
        int st = t % 3;
        h16* As = Abase + st * A_STG;
        h16* Bs = Bbase + st * B_STG;
        #pragma unroll
        for (int ks = 0; ks < 32; ks += 16) {
            u32 aH[2][4], aL[2][4], bb[4][4];
            #pragma unroll
            for (int mt = 0; mt < 2; mt++) {
                int row = wm + mt * 16 + (mi & 1) * 8 + mr;
                int col = ks + (mi >> 1) * 8;
                ldm_x4(aH[mt], smem_u32(As + 0 * 128 * AS_ROW + row * AS_ROW + col));
                ldm_x4(aL[mt], smem_u32(As + 1 * 128 * AS_ROW + row * AS_ROW + col));
            }
            #pragma unroll
            for (int nt = 0; nt < 4; nt++) {
                int brow = ks + (mi & 1) * 8 + mr;
                int bcol = wn + nt * 16 + (mi >> 1) * 8;
                ldm_x4_t(bb[nt], smem_u32(Bs + brow * BS_ROW + bcol));
            }
            // pass 1: hi term — 16 independent accumulators
            #pragma unroll
            for (int nt = 0; nt < 4; nt++)
                #pragma unroll
                for (int mt = 0; mt < 2; mt++)
                    #pragma unroll
                    for (int h2 = 0; h2 < 2; h2++)
                        mma_f16(acc[mt * 8 + nt * 2 + h2], aH[mt], bb[nt][h2 * 2], bb[nt][h2 * 2 + 1]);
            // pass 2: lo term
            #pragma unroll
            for (int nt = 0; nt < 4; nt++)
                #pragma unroll
                for (int mt = 0; mt < 2; mt++)
                    #pragma unroll
                    for (int h2 = 0; h2 < 2; h2++)
                        mma_f16(acc[mt * 8 + nt * 2 + h2], aL[mt], bb[nt][h2 * 2], bb[nt][h2 * 2 + 1]);
        }
    }

    int qr = lane >> 2;
    int qc = (lane & 3) * 2;
    #pragma unroll
    for (int mt = 0; mt < 2; mt++) {
        #pragma unroll
        for (int nt = 0; nt < 8; nt++) {
            float* c = acc[mt * 8 + nt];
            int row = bm0 + wm + mt * 16 + qr;
            int col = bn0 + wn + nt * 8 + qc;
            if (SPLITOUT) {
                *(u32*)&Cv[(size_t)row * N + col] =
                    pack_h2(__float2half_rn(c[0]), __float2half_rn(c[1]));
                *(u32*)&Cv[(size_t)(row + 8) * N + col] =
                    pack_h2(__float2half_rn(c[2]), __float2half_rn(c[3]));
            } else {
                float b0 = bias[col], b1 = bias[col + 1];
                *(float2*)&C[(size_t)row * N + col] = make_float2(c[0] + b0, c[1] + b1);
                *(float2*)&C[(size_t)(row + 8) * N + col] = make_float2(c[2] + b0, c[3] + b1);
            }
        }
    }
}

// ---------------- circulant mix (mma.sync fp16), 3-stage pipeline ----------------
// Y[i,k] = sum_j alpha[(i-j) mod N] * V[j,k]; alpha 2-term split, V single fp16.
#define VS_ROW 72                 // 144 B, 16B-aligned
#define V_STG (64*VS_ROW)         // 4608 hw per stage
#define CSMEM_HW (3*V_STG)        // 13824 hw = 27648 B

__global__ __launch_bounds__(256) void circ_k(const float* __restrict__ alpha,
                                              const float* __restrict__ x) {
    extern __shared__ h16 vsmem[];
    __shared__ u32 qp_h[2][584], qp_l[2][584];

    int i0 = blockIdx.x * 128;
    int h  = blockIdx.y;
    int b  = blockIdx.z;
    int tid = threadIdx.x;
    int wid = tid >> 5, lane = tid & 31;
    int wm = wid * 16;
    int mi = lane >> 3, mr = lane & 7;

    const float* arow = alpha + h * Nn;
    for (int s = tid; s < 576; s += 256) {
        #pragma unroll
        for (int p = 0; p < 2; p++) {
            int t0 = 2 * s + p;
            float a0 = arow[(i0 + 127 - t0) & (Nn - 1)];
            float a1 = arow[(i0 + 126 - t0) & (Nn - 1)];
            h16 h0, l0, h1, l1;
            split2h(a0, h0, l0); split2h(a1, h1, l1);
            qp_h[p][s] = pack_h2(h0, h1);
            qp_l[p][s] = pack_h2(l0, l1);
        }
    }

    auto loadV = [&](int st, int j0) {
        h16* Vs = vsmem + st * V_STG;
        #pragma unroll
        for (int i = 0; i < 2; i++) {          // 512 chunks
            int c = tid + i * 256;
            int r = c >> 3, co = (c & 7) * 8;
            const h16* src = g_v + (size_t)(b * Nn + j0 + r) * Dd + h * HS + co;
            cpa16(smem_u32(Vs + r * VS_ROW + co), src);
        }
    };

    loadV(0, 0);  CP_COMMIT();
    loadV(1, 64); CP_COMMIT();

    float acc[8][4];
    #pragma unroll
    for (int i = 0; i < 8; i++)
        #pragma unroll
        for (int j = 0; j < 4; j++) acc[i][j] = 0.f;

    int li0 = wm + (lane >> 2);
    int p   = (127 - li0) & 1;
    int sb  = (127 - li0 - p) >> 1;
    const u32* qh = qp_h[p];
    const u32* ql = qp_l[p];

    for (int t = 0; t < 16; t++) {
        if (t + 1 < 16) { CP_WAIT(1); } else { CP_WAIT(0); }
        __syncthreads();                       // also publishes qp tables at t=0
        if (t + 2 < 16) {
            loadV((t + 2) % 3, (t + 2) * 64);
            CP_COMMIT();
        }
        h16* Vs = vsmem + (t % 3) * V_STG;
        #pragma unroll
        for (int kc = 0; kc < 4; kc++) {
            int j = t * 64 + kc * 16;
            int s0 = sb + (j >> 1) + (lane & 3);
            u32 aH[4], aL[4], bb[4][4];
            aH[0] = qh[s0];     aL[0] = ql[s0];
            aH[1] = qh[s0 - 4]; aL[1] = ql[s0 - 4];
            aH[2] = qh[s0 + 4]; aL[2] = ql[s0 + 4];
            aH[3] = aH[0];      aL[3] = aL[0];
            #pragma unroll
            for (int n2 = 0; n2 < 4; n2++) {
                int brow = kc * 16 + (mi & 1) * 8 + mr;
                int bcol = n2 * 16 + (mi >> 1) * 8;
                ldm_x4_t(bb[n2], smem_u32(Vs + brow * VS_ROW + bcol));
            }
            // pass 1: alpha hi — 8 independent accumulators
            #pragma unroll
            for (int n2 = 0; n2 < 4; n2++)
                #pragma unroll
                for (int h2 = 0; h2 < 2; h2++)
                    mma_f16(acc[n2 * 2 + h2], aH, bb[n2][h2 * 2], bb[n2][h2 * 2 + 1]);
            // pass 2: alpha lo
            #pragma unroll
            for (int n2 = 0; n2 < 4; n2++)
                #pragma unroll
                for (int h2 = 0; h2 < 2; h2++)
                    mma_f16(acc[n2 * 2 + h2], aL, bb[n2][h2 * 2], bb[n2][h2 * 2 + 1]);
        }
    }

    int qr = lane >> 2;
    int qc = (lane & 3) * 2;
    #pragma unroll
    for (int nt = 0; nt < 8; nt++) {
        float* c = acc[nt];
        #pragma unroll
        for (int half = 0; half < 2; half++) {
            int row = b * Nn + i0 + wm + qr + half * 8;
            int col = h * HS + nt * 8 + qc;
            size_t off = (size_t)row * Dd + col;
            float2 xv = *(const float2*)&x[off];
            float o0 = c[half * 2 + 0] + xv.x;
            float o1 = c[half * 2 + 1] + xv.y;
            *(float2*)&g_x2[off] = make_float2(o0, o1);
            h16 h0, l0, h1, l1;
            split2h(o0, h0, l0); split2h(o1, h1, l1);
            *(u32*)&g_ah[off] = pack_h2(h0, h1);
            *(u32*)&g_al[off] = pack_h2(l0, l1);
        }
    }
}

extern "C" void kernel_launch(void* const* d_in, const int* in_sizes, int n_in,
                              void* d_out, int out_size) {
    const float* x         = (const float*)d_in[0];
    const float* ln1_scale = (const float*)d_in[1];
    const float* ln1_bias  = (const float*)d_in[2];
    const float* Wv        = (const float*)d_in[3];
    const float* alpha     = (const float*)d_in[4];
    const float* Wf        = (const float*)d_in[5];
    const float* bf        = (const float*)d_in[6];
    const float* lnf_scale = (const float*)d_in[7];
    const float* lnf_bias  = (const float*)d_in[8];
    float* out = (float*)d_out;

    float *t;
    h16 *wh, *v;
    cudaGetSymbolAddress((void**)&t,  g_t);
    cudaGetSymbolAddress((void**)&wh, g_wh);
    cudaGetSymbolAddress((void**)&v,  g_v);

    const int GSMEM = GSMEM_HW * (int)sizeof(h16);   // 87552
    const int CSMEM = CSMEM_HW * (int)sizeof(h16);   // 27648
    cudaFuncSetAttribute(gemm_f16<0>, cudaFuncAttributeMaxDynamicSharedMemorySize, GSMEM);
    cudaFuncSetAttribute(gemm_f16<1>, cudaFuncAttributeMaxDynamicSharedMemorySize, GSMEM);
    cudaFuncSetAttribute(circ_k, cudaFuncAttributeMaxDynamicSharedMemorySize, CSMEM);

    dim3 ggrid(Dd / 128, ROWS / 128);

    wsplit_wv_k<<<(D2 + 255) / 256, 256>>>(Wv);
    wsplit_wf_k<<<(2 * D2 + 255) / 256, 256>>>(Wf);
    // xn = LN(x) -> split
    ln_k<0, 1, 0><<<ROWS, 256>>>(x, ln1_scale, ln1_bias, nullptr);
    // v = xn @ Wcat -> single fp16
    gemm_f16<1><<<ggrid, 256, GSMEM>>>(wh, nullptr, nullptr, v, ROWS, Dd, Dd);
    // x2 = x + circ(alpha, v)  -> f32 + split
    circ_k<<<dim3(Nn / 128, Hh, Bb), 256, CSMEM>>>(alpha, x);
    // FFN0: t = x2 @ Wf0 + bf0
    gemm_f16<0><<<ggrid, 256, GSMEM>>>(wh + D2, bf, t, nullptr, ROWS, Dd, Dd);
    // z0 = swish(LN(t)) -> split
    ln_k<1, 1, 0><<<ROWS, 256>>>(t, lnf_scale, lnf_bias, nullptr);
    // FFN1: t = z0 @ Wf1 + bf1
    gemm_f16<0><<<ggrid, 256, GSMEM>>>(wh + 2 * D2, bf + Dd, t, nullptr, ROWS, Dd, Dd);
    // z1 = swish(LN(t)); out = log_cosh(z1 + x2)
    ln_k<1, 0, 1><<<ROWS, 256>>>(t, lnf_scale + Dd, lnf_bias + Dd, out);
}

// round 15
// speedup vs baseline: 4.0011x; 1.1649x over previous
#include <cuda_runtime.h>
#include <cuda_fp16.h>
#include <math.h>

#define Bb 16
#define Nn 1024
#define Dd 768
#define Hh 12
#define HS 64
#define ROWS (Bb*Nn)          // 16384
#define TOT  (Bb*Nn*Dd)       // 12,582,912
#define D2   (Dd*Dd)
#define EPS  1e-6f

typedef unsigned long long u64;
typedef unsigned int u32;
typedef __half h16;

// scratch (no allocations allowed)
__device__ float g_x2[TOT];
__device__ float g_t[TOT];
__device__ h16 g_v[TOT];                  // v single fp16
__device__ h16 g_ah[TOT];                 // activation split hi (xn -> x2 -> z0)
__device__ h16 g_al[TOT];                 // activation split lo
__device__ h16 g_wh[3*D2];                // weights single fp16 [k][n]: [wcat, wf0, wf1]

// ---------------- helpers ----------------
__device__ __forceinline__ void split2h(float x, h16& h, h16& l) {
    h = __float2half_rn(x);
    l = __float2half_rn(x - __half2float(h));
}
__device__ __forceinline__ u32 pack_h2(h16 a, h16 b) {
    __half2 p; p.x = a; p.y = b;
    return *reinterpret_cast<u32*>(&p);
}
__device__ __forceinline__ u32 smem_u32(const void* p) {
    return (u32)__cvta_generic_to_shared(p);
}
__device__ __forceinline__ void cpa16(u32 dst, const void* src) {
    asm volatile("cp.async.cg.shared.global [%0], [%1], 16;" :: "r"(dst), "l"(src));
}
#define CP_COMMIT() asm volatile("cp.async.commit_group;")
#define CP_WAIT(n)  asm volatile("cp.async.wait_group %0;" :: "n"(n))

__device__ __forceinline__ void ldm_x4(u32 r[4], u32 addr) {
    asm volatile("ldmatrix.sync.aligned.m8n8.x4.shared.b16 {%0,%1,%2,%3}, [%4];"
                 : "=r"(r[0]), "=r"(r[1]), "=r"(r[2]), "=r"(r[3]) : "r"(addr));
}
__device__ __forceinline__ void ldm_x4_t(u32 r[4], u32 addr) {
    asm volatile("ldmatrix.sync.aligned.m8n8.x4.trans.shared.b16 {%0,%1,%2,%3}, [%4];"
                 : "=r"(r[0]), "=r"(r[1]), "=r"(r[2]), "=r"(r[3]) : "r"(addr));
}
__device__ __forceinline__ void mma_f16(float c[4], const u32 a[4], u32 b0, u32 b1) {
    asm volatile("mma.sync.aligned.m16n8k16.row.col.f32.f16.f16.f32 "
                 "{%0,%1,%2,%3}, {%4,%5,%6,%7}, {%8,%9}, {%0,%1,%2,%3};"
                 : "+f"(c[0]), "+f"(c[1]), "+f"(c[2]), "+f"(c[3])
                 : "r"(a[0]), "r"(a[1]), "r"(a[2]), "r"(a[3]), "r"(b0), "r"(b1));
}

// ---------------- weight prep (single fp16) ----------------
__global__ void wsplit_wv_k(const float* __restrict__ Wv) {
    int idx = blockIdx.x * 256 + threadIdx.x;
    if (idx >= D2) return;
    int col = idx % Dd;            // h*HS + k
    int d   = idx / Dd;
    int h = col / HS, k = col % HS;
    g_wh[idx] = __float2half_rn(Wv[((size_t)h * Dd + d) * HS + k]);
}
__global__ void wsplit_wf_k(const float* __restrict__ Wf) {
    int idx = blockIdx.x * 256 + threadIdx.x;
    if (idx >= 2 * D2) return;
    g_wh[D2 + idx] = __float2half_rn(Wf[idx]);
}

// ---------------- layernorm (+swish) ----------------
__inline__ __device__ float warpsum(float v) {
    #pragma unroll
    for (int o = 16; o; o >>= 1) v += __shfl_xor_sync(0xffffffffu, v, o);
    return v;
}

// WSPLIT: 0 none, 1 hi+lo, 2 hi only.  FINAL: out = log_cosh(val + x2)
template <int ACT, int WSPLIT, int FINAL>
__global__ __launch_bounds__(256) void ln_k(const float* __restrict__ in,
                                            const float* __restrict__ sc,
                                            const float* __restrict__ bi,
                                            float* __restrict__ outf) {
    int row = blockIdx.x;
    const float* r = in + (size_t)row * Dd;
    int t = threadIdx.x;
    float v0 = r[t], v1 = r[t + 256], v2 = r[t + 512];
    float s = v0 + v1 + v2;
    float q = v0 * v0 + v1 * v1 + v2 * v2;
    __shared__ float sh[16];
    float ws = warpsum(s), wq = warpsum(q);
    int w = t >> 5, l = t & 31;
    if (l == 0) { sh[w] = ws; sh[8 + w] = wq; }
    __syncthreads();
    float ssum = 0.f, ssq = 0.f;
    #pragma unroll
    for (int i = 0; i < 8; i++) { ssum += sh[i]; ssq += sh[8 + i]; }
    float mean = ssum * (1.0f / Dd);
    float var  = ssq * (1.0f / Dd) - mean * mean;
    float inv  = rsqrtf(var + EPS);
    #pragma unroll
    for (int kk = 0; kk < 3; kk++) {
        int c = t + kk * 256;
        float v = (kk == 0 ? v0 : (kk == 1 ? v1 : v2));
        float val = (v - mean) * inv * sc[c] + bi[c];
        if (ACT) val = val / (1.0f + expf(-val));
        size_t off = (size_t)row * Dd + c;
        if (WSPLIT == 1) split2h(val, g_ah[off], g_al[off]);
        if (WSPLIT == 2) g_ah[off] = __float2half_rn(val);
        if (FINAL) {
            float o = val + g_x2[off];
            float a = fabsf(o);
            outf[off] = a + log1pf(expf(-2.0f * a)) - 0.69314718055994530942f;
        }
    }
}

// ---------------- tensor-core GEMM (mma.sync fp16), 3-stage pipeline ----------------
// TERMS=2: C = (Ah+Al)@Bh ; TERMS=1: C = Ah@Bh.  B single fp16 row-major [K,N].
#define AS_ROW 40                 // 80 B rows, 16B-aligned
#define BS_ROW 136                // 272 B rows
#define A_STG (2*128*AS_ROW)      // 10240 hw
#define B_STG (32*BS_ROW)         // 4352 hw
#define GSMEM_HW (3*(A_STG + B_STG))   // 43776 hw = 87552 B

template <int SPLITOUT, int TERMS>
__global__ __launch_bounds__(256) void gemm_f16(const h16* __restrict__ Bh,
                                                const float* __restrict__ bias,
                                                float* __restrict__ C,
                                                h16* __restrict__ Cv,
                                                int M, int N, int K) {
    extern __shared__ h16 smem[];
    h16* Abase = smem;
    h16* Bbase = smem + 3 * A_STG;

    int tid = threadIdx.x;
    int wid = tid >> 5, lane = tid & 31;
    int wm = (wid & 3) * 32;
    int wn = (wid >> 2) * 64;
    int bm0 = blockIdx.y * 128;
    int bn0 = blockIdx.x * 128;

    float acc[16][4];
    #pragma unroll
    for (int i = 0; i < 16; i++)
        #pragma unroll
        for (int j = 0; j < 4; j++) acc[i][j] = 0.f;

    int mi = lane >> 3;
    int mr = lane & 7;

    auto load_stage = [&](int st, int kt) {
        h16* As = Abase + st * A_STG;
        h16* Bs = Bbase + st * B_STG;
        #pragma unroll
        for (int i = 0; i < 2 * TERMS; i++) {   // A: hi (and lo if TERMS=2)
            int c = tid + i * 256;
            int hl = c >> 9, cc = c & 511;
            int row = cc >> 2, col = (cc & 3) * 8;
            const h16* src = (hl ? g_al : g_ah) + (size_t)(bm0 + row) * K + kt + col;
            cpa16(smem_u32(As + hl * 128 * AS_ROW + row * AS_ROW + col), src);
        }
        #pragma unroll
        for (int i = 0; i < 2; i++) {        // B: 512 chunks
            int c = tid + i * 256;
            int row = c >> 4, col = (c & 15) * 8;
            const h16* src = Bh + (size_t)(kt + row) * N + bn0 + col;
            cpa16(smem_u32(Bs + row * BS_ROW + col), src);
        }
    };

    const int NT = Dd / 32;   // 24 k-tiles
    load_stage(0, 0);  CP_COMMIT();
    load_stage(1, 32); CP_COMMIT();

    for (int t = 0; t < NT; t++) {
        if (t + 1 < NT) { CP_WAIT(1); } else { CP_WAIT(0); }
        __syncthreads();
        if (t + 2 < NT) {
            load_stage((t + 2) % 3, (t + 2) * 32);
            CP_COMMIT();
        }
        int st = t % 3;
        h16* As = Abase + st * A_STG;
        h16* Bs = Bbase + st * B_STG;
        #pragma unroll
        for (int ks = 0; ks < 32; ks += 16) {
            u32 aH[2][4], aL[2][4], bb[4][4];
            #pragma unroll
            for (int mt = 0; mt < 2; mt++) {
                int row = wm + mt * 16 + (mi & 1) * 8 + mr;
                int col = ks + (mi >> 1) * 8;
                ldm_x4(aH[mt], smem_u32(As + 0 * 128 * AS_ROW + row * AS_ROW + col));
                if (TERMS == 2)
                    ldm_x4(aL[mt], smem_u32(As + 1 * 128 * AS_ROW + row * AS_ROW + col));
            }
            #pragma unroll
            for (int nt = 0; nt < 4; nt++) {
                int brow = ks + (mi & 1) * 8 + mr;
                int bcol = wn + nt * 16 + (mi >> 1) * 8;
                ldm_x4_t(bb[nt], smem_u32(Bs + brow * BS_ROW + bcol));
            }
            // pass 1: hi term — 16 independent accumulators
            #pragma unroll
            for (int nt = 0; nt < 4; nt++)
                #pragma unroll
                for (int mt = 0; mt < 2; mt++)
                    #pragma unroll
                    for (int h2 = 0; h2 < 2; h2++)
                        mma_f16(acc[mt * 8 + nt * 2 + h2], aH[mt], bb[nt][h2 * 2], bb[nt][h2 * 2 + 1]);
            // pass 2: lo term
            if (TERMS == 2) {
                #pragma unroll
                for (int nt = 0; nt < 4; nt++)
                    #pragma unroll
                    for (int mt = 0; mt < 2; mt++)
                        #pragma unroll
                        for (int h2 = 0; h2 < 2; h2++)
                            mma_f16(acc[mt * 8 + nt * 2 + h2], aL[mt], bb[nt][h2 * 2], bb[nt][h2 * 2 + 1]);
            }
        }
    }

    int qr = lane >> 2;
    int qc = (lane & 3) * 2;
    #pragma unroll
    for (int mt = 0; mt < 2; mt++) {
        #pragma unroll
        for (int nt = 0; nt < 8; nt++) {
            float* c = acc[mt * 8 + nt];
            int row = bm0 + wm + mt * 16 + qr;
            int col = bn0 + wn + nt * 8 + qc;
            if (SPLITOUT) {
                *(u32*)&Cv[(size_t)row * N + col] =
                    pack_h2(__float2half_rn(c[0]), __float2half_rn(c[1]));
                *(u32*)&Cv[(size_t)(row + 8) * N + col] =
                    pack_h2(__float2half_rn(c[2]), __float2half_rn(c[3]));
            } else {
                float b0 = bias[col], b1 = bias[col + 1];
                *(float2*)&C[(size_t)row * N + col] = make_float2(c[0] + b0, c[1] + b1);
                *(float2*)&C[(size_t)(row + 8) * N + col] = make_float2(c[2] + b0, c[3] + b1);
            }
        }
    }
}

// ---------------- circulant mix (mma.sync fp16, single term), 3-stage pipeline ----------------
// Y[i,k] = sum_j alpha[(i-j) mod N] * V[j,k]; alpha and V single fp16.
#define VS_ROW 72                 // 144 B, 16B-aligned
#define V_STG (64*VS_ROW)         // 4608 hw per stage
#define CSMEM_HW (3*V_STG)        // 13824 hw = 27648 B

__global__ __launch_bounds__(256) void circ_k(const float* __restrict__ alpha,
                                              const float* __restrict__ x) {
    extern __shared__ h16 vsmem[];
    __shared__ u32 qp_h[2][584];

    int i0 = blockIdx.x * 128;
    int h  = blockIdx.y;
    int b  = blockIdx.z;
    int tid = threadIdx.x;
    int wid = tid >> 5, lane = tid & 31;
    int wm = wid * 16;
    int mi = lane >> 3, mr = lane & 7;

    const float* arow = alpha + h * Nn;
    for (int s = tid; s < 576; s += 256) {
        #pragma unroll
        for (int p = 0; p < 2; p++) {
            int t0 = 2 * s + p;
            float a0 = arow[(i0 + 127 - t0) & (Nn - 1)];
            float a1 = arow[(i0 + 126 - t0) & (Nn - 1)];
            qp_h[p][s] = pack_h2(__float2half_rn(a0), __float2half_rn(a1));
        }
    }

    auto loadV = [&](int st, int j0) {
        h16* Vs = vsmem + st * V_STG;
        #pragma unroll
        for (int i = 0; i < 2; i++) {          // 512 chunks
            int c = tid + i * 256;
            int r = c >> 3, co = (c & 7) * 8;
            const h16* src = g_v + (size_t)(b * Nn + j0 + r) * Dd + h * HS + co;
            cpa16(smem_u32(Vs + r * VS_ROW + co), src);
        }
    };

    loadV(0, 0);  CP_COMMIT();
    loadV(1, 64); CP_COMMIT();

    float acc[8][4];
    #pragma unroll
    for (int i = 0; i < 8; i++)
        #pragma unroll
        for (int j = 0; j < 4; j++) acc[i][j] = 0.f;

    int li0 = wm + (lane >> 2);
    int p   = (127 - li0) & 1;
    int sb  = (127 - li0 - p) >> 1;
    const u32* qh = qp_h[p];

    for (int t = 0; t < 16; t++) {
        if (t + 1 < 16) { CP_WAIT(1); } else { CP_WAIT(0); }
        __syncthreads();                       // also publishes qp table at t=0
        if (t + 2 < 16) {
            loadV((t + 2) % 3, (t + 2) * 64);
            CP_COMMIT();
        }
        h16* Vs = vsmem + (t % 3) * V_STG;
        #pragma unroll
        for (int kc = 0; kc < 4; kc++) {
            int j = t * 64 + kc * 16;
            int s0 = sb + (j >> 1) + (lane & 3);
            u32 aH[4], bb[4][4];
            aH[0] = qh[s0];
            aH[1] = qh[s0 - 4];
            aH[2] = qh[s0 + 4];
            aH[3] = aH[0];
            #pragma unroll
            for (int n2 = 0; n2 < 4; n2++) {
                int brow = kc * 16 + (mi & 1) * 8 + mr;
                int bcol = n2 * 16 + (mi >> 1) * 8;
                ldm_x4_t(bb[n2], smem_u32(Vs + brow * VS_ROW + bcol));
            }
            #pragma unroll
            for (int n2 = 0; n2 < 4; n2++)
                #pragma unroll
                for (int h2 = 0; h2 < 2; h2++)
                    mma_f16(acc[n2 * 2 + h2], aH, bb[n2][h2 * 2], bb[n2][h2 * 2 + 1]);
        }
    }

    int qr = lane >> 2;
    int qc = (lane & 3) * 2;
    #pragma unroll
    for (int nt = 0; nt < 8; nt++) {
        float* c = acc[nt];
        #pragma unroll
        for (int half = 0; half < 2; half++) {
            int row = b * Nn + i0 + wm + qr + half * 8;
            int col = h * HS + nt * 8 + qc;
            size_t off = (size_t)row * Dd + col;
            float2 xv = *(const float2*)&x[off];
            float o0 = c[half * 2 + 0] + xv.x;
            float o1 = c[half * 2 + 1] + xv.y;
            *(float2*)&g_x2[off] = make_float2(o0, o1);
            h16 h0, l0, h1, l1;
            split2h(o0, h0, l0); split2h(o1, h1, l1);
            *(u32*)&g_ah[off] = pack_h2(h0, h1);
            *(u32*)&g_al[off] = pack_h2(l0, l1);
        }
    }
}

extern "C" void kernel_launch(void* const* d_in, const int* in_sizes, int n_in,
                              void* d_out, int out_size) {
    const float* x         = (const float*)d_in[0];
    const float* ln1_scale = (const float*)d_in[1];
    const float* ln1_bias  = (const float*)d_in[2];
    const float* Wv        = (const float*)d_in[3];
    const float* alpha     = (const float*)d_in[4];
    const float* Wf        = (const float*)d_in[5];
    const float* bf        = (const float*)d_in[6];
    const float* lnf_scale = (const float*)d_in[7];
    const float* lnf_bias  = (const float*)d_in[8];
    float* out = (float*)d_out;

    float *t;
    h16 *wh, *v;
    cudaGetSymbolAddress((void**)&t,  g_t);
    cudaGetSymbolAddress((void**)&wh, g_wh);
    cudaGetSymbolAddress((void**)&v,  g_v);

    const int GSMEM = GSMEM_HW * (int)sizeof(h16);   // 87552
    const int CSMEM = CSMEM_HW * (int)sizeof(h16);   // 27648
    cudaFuncSetAttribute((const void*)gemm_f16<0, 2>, cudaFuncAttributeMaxDynamicSharedMemorySize, GSMEM);
    cudaFuncSetAttribute((const void*)gemm_f16<1, 1>, cudaFuncAttributeMaxDynamicSharedMemorySize, GSMEM);
    cudaFuncSetAttribute((const void*)circ_k, cudaFuncAttributeMaxDynamicSharedMemorySize, CSMEM);

    dim3 ggrid(Dd / 128, ROWS / 128);

    wsplit_wv_k<<<(D2 + 255) / 256, 256>>>(Wv);
    wsplit_wf_k<<<(2 * D2 + 255) / 256, 256>>>(Wf);
    // xn = LN(x) -> hi only (single-term V projection)
    ln_k<0, 2, 0><<<ROWS, 256>>>(x, ln1_scale, ln1_bias, nullptr);
    // v = xn @ Wcat -> single fp16 (1-term)
    gemm_f16<1, 1><<<ggrid, 256, GSMEM>>>(wh, nullptr, nullptr, v, ROWS, Dd, Dd);
    // x2 = x + circ(alpha, v)  -> f32 + split
    circ_k<<<dim3(Nn / 128, Hh, Bb), 256, CSMEM>>>(alpha, x);
    // FFN0: t = x2 @ Wf0 + bf0 (2-term)
    gemm_f16<0, 2><<<ggrid, 256, GSMEM>>>(wh + D2, bf, t, nullptr, ROWS, Dd, Dd);
    // z0 = swish(LN(t)) -> split
    ln_k<1, 1, 0><<<ROWS, 256>>>(t, lnf_scale, lnf_bias, nullptr);
    // FFN1: t = z0 @ Wf1 + bf1 (2-term)
    gemm_f16<0, 2><<<ggrid, 256, GSMEM>>>(wh + 2 * D2, bf + Dd, t, nullptr, ROWS, Dd, Dd);
    // z1 = swish(LN(t)); out = log_cosh(z1 + x2)
    ln_k<1, 0, 1><<<ROWS, 256>>>(t, lnf_scale + Dd, lnf_bias + Dd, out);
}

// round 16
// speedup vs baseline: 5.0883x; 1.2717x over previous
#include <cuda_runtime.h>
#include <cuda_fp16.h>
#include <math.h>

#define Bb 16
#define Nn 1024
#define Dd 768
#define Hh 12
#define HS 64
#define ROWS (Bb*Nn)          // 16384
#define TOT  (Bb*Nn*Dd)       // 12,582,912
#define D2   (Dd*Dd)
#define EPS  1e-6f

typedef unsigned long long u64;
typedef unsigned int u32;
typedef __half h16;

// scratch (no allocations allowed)
__device__ float g_x2[TOT];
__device__ float g_t[TOT];
__device__ h16 g_v[TOT];                  // v single fp16
__device__ h16 g_ah[TOT];                 // activation fp16 (xn -> x2 -> z0)
__device__ h16 g_wh[3*D2];                // weights single fp16 [k][n]: [wcat, wf0, wf1]

// ---------------- helpers ----------------
__device__ __forceinline__ u32 pack_h2(h16 a, h16 b) {
    __half2 p; p.x = a; p.y = b;
    return *reinterpret_cast<u32*>(&p);
}
__device__ __forceinline__ u32 smem_u32(const void* p) {
    return (u32)__cvta_generic_to_shared(p);
}
__device__ __forceinline__ void cpa16(u32 dst, const void* src) {
    asm volatile("cp.async.cg.shared.global [%0], [%1], 16;" :: "r"(dst), "l"(src));
}
#define CP_COMMIT() asm volatile("cp.async.commit_group;")
#define CP_WAIT(n)  asm volatile("cp.async.wait_group %0;" :: "n"(n))

__device__ __forceinline__ void ldm_x4(u32 r[4], u32 addr) {
    asm volatile("ldmatrix.sync.aligned.m8n8.x4.shared.b16 {%0,%1,%2,%3}, [%4];"
                 : "=r"(r[0]), "=r"(r[1]), "=r"(r[2]), "=r"(r[3]) : "r"(addr));
}
__device__ __forceinline__ void ldm_x4_t(u32 r[4], u32 addr) {
    asm volatile("ldmatrix.sync.aligned.m8n8.x4.trans.shared.b16 {%0,%1,%2,%3}, [%4];"
                 : "=r"(r[0]), "=r"(r[1]), "=r"(r[2]), "=r"(r[3]) : "r"(addr));
}
__device__ __forceinline__ void mma_f16(float c[4], const u32 a[4], u32 b0, u32 b1) {
    asm volatile("mma.sync.aligned.m16n8k16.row.col.f32.f16.f16.f32 "
                 "{%0,%1,%2,%3}, {%4,%5,%6,%7}, {%8,%9}, {%0,%1,%2,%3};"
                 : "+f"(c[0]), "+f"(c[1]), "+f"(c[2]), "+f"(c[3])
                 : "r"(a[0]), "r"(a[1]), "r"(a[2]), "r"(a[3]), "r"(b0), "r"(b1));
}

// ---------------- weight prep (single fp16) ----------------
__global__ void wsplit_wv_k(const float* __restrict__ Wv) {
    int idx = blockIdx.x * 256 + threadIdx.x;
    if (idx >= D2) return;
    int col = idx % Dd;            // h*HS + k
    int d   = idx / Dd;
    int h = col / HS, k = col % HS;
    g_wh[idx] = __float2half_rn(Wv[((size_t)h * Dd + d) * HS + k]);
}
__global__ void wsplit_wf_k(const float* __restrict__ Wf) {
    int idx = blockIdx.x * 256 + threadIdx.x;
    if (idx >= 2 * D2) return;
    g_wh[D2 + idx] = __float2half_rn(Wf[idx]);
}

// ---------------- layernorm (+swish) ----------------
__inline__ __device__ float warpsum(float v) {
    #pragma unroll
    for (int o = 16; o; o >>= 1) v += __shfl_xor_sync(0xffffffffu, v, o);
    return v;
}

// WH: write fp16 to g_ah.  FINAL: out = log_cosh(val + x2)
template <int ACT, int WH, int FINAL>
__global__ __launch_bounds__(256) void ln_k(const float* __restrict__ in,
                                            const float* __restrict__ sc,
                                            const float* __restrict__ bi,
                                            float* __restrict__ outf) {
    int row = blockIdx.x;
    const float* r = in + (size_t)row * Dd;
    int t = threadIdx.x;
    float v0 = r[t], v1 = r[t + 256], v2 = r[t + 512];
    float s = v0 + v1 + v2;
    float q = v0 * v0 + v1 * v1 + v2 * v2;
    __shared__ float sh[16];
    float ws = warpsum(s), wq = warpsum(q);
    int w = t >> 5, l = t & 31;
    if (l == 0) { sh[w] = ws; sh[8 + w] = wq; }
    __syncthreads();
    float ssum = 0.f, ssq = 0.f;
    #pragma unroll
    for (int i = 0; i < 8; i++) { ssum += sh[i]; ssq += sh[8 + i]; }
    float mean = ssum * (1.0f / Dd);
    float var  = ssq * (1.0f / Dd) - mean * mean;
    float inv  = rsqrtf(var + EPS);
    #pragma unroll
    for (int kk = 0; kk < 3; kk++) {
        int c = t + kk * 256;
        float v = (kk == 0 ? v0 : (kk == 1 ? v1 : v2));
        float val = (v - mean) * inv * sc[c] + bi[c];
        if (ACT) val = val / (1.0f + expf(-val));
        size_t off = (size_t)row * Dd + c;
        if (WH) g_ah[off] = __float2half_rn(val);
        if (FINAL) {
            float o = val + g_x2[off];
            float a = fabsf(o);
            outf[off] = a + log1pf(expf(-2.0f * a)) - 0.69314718055994530942f;
        }
    }
}

// ---------------- tensor-core GEMM (mma.sync fp16, 1-term), 3-stage pipeline ----------------
// C = Ah @ Bh (+bias); A fp16 g_ah [M,K], B single fp16 row-major [K,N].
#define AS_ROW 40                 // 80 B rows, 16B-aligned
#define BS_ROW 136                // 272 B rows
#define A_STG (128*AS_ROW)        // 5120 hw
#define B_STG (32*BS_ROW)         // 4352 hw
#define GSMEM_HW (3*(A_STG + B_STG))   // 28416 hw = 56832 B

template <int SPLITOUT>
__global__ __launch_bounds__(256) void gemm_f16(const h16* __restrict__ Bh,
                                                const float* __restrict__ bias,
                                                float* __restrict__ C,
                                                h16* __restrict__ Cv,
                                                int M, int N, int K) {
    extern __shared__ h16 smem[];
    h16* Abase = smem;
    h16* Bbase = smem + 3 * A_STG;

    int tid = threadIdx.x;
    int wid = tid >> 5, lane = tid & 31;
    int wm = (wid & 3) * 32;
    int wn = (wid >> 2) * 64;
    int bm0 = blockIdx.y * 128;
    int bn0 = blockIdx.x * 128;

    float acc[16][4];
    #pragma unroll
    for (int i = 0; i < 16; i++)
        #pragma unroll
        for (int j = 0; j < 4; j++) acc[i][j] = 0.f;

    int mi = lane >> 3;
    int mr = lane & 7;

    auto load_stage = [&](int st, int kt) {
        h16* As = Abase + st * A_STG;
        h16* Bs = Bbase + st * B_STG;
        #pragma unroll
        for (int i = 0; i < 2; i++) {        // A: 512 chunks
            int c = tid + i * 256;
            int row = c >> 2, col = (c & 3) * 8;
            const h16* src = g_ah + (size_t)(bm0 + row) * K + kt + col;
            cpa16(smem_u32(As + row * AS_ROW + col), src);
        }
        #pragma unroll
        for (int i = 0; i < 2; i++) {        // B: 512 chunks
            int c = tid + i * 256;
            int row = c >> 4, col = (c & 15) * 8;
            const h16* src = Bh + (size_t)(kt + row) * N + bn0 + col;
            cpa16(smem_u32(Bs + row * BS_ROW + col), src);
        }
    };

    const int NT = Dd / 32;   // 24 k-tiles
    load_stage(0, 0);  CP_COMMIT();
    load_stage(1, 32); CP_COMMIT();

    for (int t = 0; t < NT; t++) {
        if (t + 1 < NT) { CP_WAIT(1); } else { CP_WAIT(0); }
        __syncthreads();
        if (t + 2 < NT) {
            load_stage((t + 2) % 3, (t + 2) * 32);
            CP_COMMIT();
        }
        int st = t % 3;
        h16* As = Abase + st * A_STG;
        h16* Bs = Bbase + st * B_STG;
        #pragma unroll
        for (int ks = 0; ks < 32; ks += 16) {
            u32 aH[2][4], bb[4][4];
            #pragma unroll
            for (int mt = 0; mt < 2; mt++) {
                int row = wm + mt * 16 + (mi & 1) * 8 + mr;
                int col = ks + (mi >> 1) * 8;
                ldm_x4(aH[mt], smem_u32(As + row * AS_ROW + col));
            }
            #pragma unroll
            for (int nt = 0; nt < 4; nt++) {
                int brow = ks + (mi & 1) * 8 + mr;
                int bcol = wn + nt * 16 + (mi >> 1) * 8;
                ldm_x4_t(bb[nt], smem_u32(Bs + brow * BS_ROW + bcol));
            }
            #pragma unroll
            for (int nt = 0; nt < 4; nt++)
                #pragma unroll
                for (int mt = 0; mt < 2; mt++)
                    #pragma unroll
                    for (int h2 = 0; h2 < 2; h2++)
                        mma_f16(acc[mt * 8 + nt * 2 + h2], aH[mt], bb[nt][h2 * 2], bb[nt][h2 * 2 + 1]);
        }
    }

    int qr = lane >> 2;
    int qc = (lane & 3) * 2;
    #pragma unroll
    for (int mt = 0; mt < 2; mt++) {
        #pragma unroll
        for (int nt = 0; nt < 8; nt++) {
            float* c = acc[mt * 8 + nt];
            int row = bm0 + wm + mt * 16 + qr;
            int col = bn0 + wn + nt * 8 + qc;
            if (SPLITOUT) {
                *(u32*)&Cv[(size_t)row * N + col] =
                    pack_h2(__float2half_rn(c[0]), __float2half_rn(c[1]));
                *(u32*)&Cv[(size_t)(row + 8) * N + col] =
                    pack_h2(__float2half_rn(c[2]), __float2half_rn(c[3]));
            } else {
                float b0 = bias[col], b1 = bias[col + 1];
                *(float2*)&C[(size_t)row * N + col] = make_float2(c[0] + b0, c[1] + b1);
                *(float2*)&C[(size_t)(row + 8) * N + col] = make_float2(c[2] + b0, c[3] + b1);
            }
        }
    }
}

// ---------------- circulant mix (mma.sync fp16, single term), 3-stage pipeline ----------------
// Y[i,k] = sum_j alpha[(i-j) mod N] * V[j,k]; alpha and V single fp16.
#define VS_ROW 72                 // 144 B, 16B-aligned
#define V_STG (64*VS_ROW)         // 4608 hw per stage
#define CSMEM_HW (3*V_STG)        // 13824 hw = 27648 B

__global__ __launch_bounds__(256) void circ_k(const float* __restrict__ alpha,
                                              const float* __restrict__ x) {
    extern __shared__ h16 vsmem[];
    __shared__ u32 qp_h[2][584];

    int i0 = blockIdx.x * 128;
    int h  = blockIdx.y;
    int b  = blockIdx.z;
    int tid = threadIdx.x;
    int wid = tid >> 5, lane = tid & 31;
    int wm = wid * 16;
    int mi = lane >> 3, mr = lane & 7;

    const float* arow = alpha + h * Nn;
    for (int s = tid; s < 576; s += 256) {
        #pragma unroll
        for (int p = 0; p < 2; p++) {
            int t0 = 2 * s + p;
            float a0 = arow[(i0 + 127 - t0) & (Nn - 1)];
            float a1 = arow[(i0 + 126 - t0) & (Nn - 1)];
            qp_h[p][s] = pack_h2(__float2half_rn(a0), __float2half_rn(a1));
        }
    }

    auto loadV = [&](int st, int j0) {
        h16* Vs = vsmem + st * V_STG;
        #pragma unroll
        for (int i = 0; i < 2; i++) {          // 512 chunks
            int c = tid + i * 256;
            int r = c >> 3, co = (c & 7) * 8;
            const h16* src = g_v + (size_t)(b * Nn + j0 + r) * Dd + h * HS + co;
            cpa16(smem_u32(Vs + r * VS_ROW + co), src);
        }
    };

    loadV(0, 0);  CP_COMMIT();
    loadV(1, 64); CP_COMMIT();

    float acc[8][4];
    #pragma unroll
    for (int i = 0; i < 8; i++)
        #pragma unroll
        for (int j = 0; j < 4; j++) acc[i][j] = 0.f;

    int li0 = wm + (lane >> 2);
    int p   = (127 - li0) & 1;
    int sb  = (127 - li0 - p) >> 1;
    const u32* qh = qp_h[p];

    for (int t = 0; t < 16; t++) {
        if (t + 1 < 16) { CP_WAIT(1); } else { CP_WAIT(0); }
        __syncthreads();                       // also publishes qp table at t=0
        if (t + 2 < 16) {
            loadV((t + 2) % 3, (t + 2) * 64);
            CP_COMMIT();
        }
        h16* Vs = vsmem + (t % 3) * V_STG;
        #pragma unroll
        for (int kc = 0; kc < 4; kc++) {
            int j = t * 64 + kc * 16;
            int s0 = sb + (j >> 1) + (lane & 3);
            u32 aH[4], bb[4][4];
            aH[0] = qh[s0];
            aH[1] = qh[s0 - 4];
            aH[2] = qh[s0 + 4];
            aH[3] = aH[0];
            #pragma unroll
            for (int n2 = 0; n2 < 4; n2++) {
                int brow = kc * 16 + (mi & 1) * 8 + mr;
                int bcol = n2 * 16 + (mi >> 1) * 8;
                ldm_x4_t(bb[n2], smem_u32(Vs + brow * VS_ROW + bcol));
            }
            #pragma unroll
            for (int n2 = 0; n2 < 4; n2++)
                #pragma unroll
                for (int h2 = 0; h2 < 2; h2++)
                    mma_f16(acc[n2 * 2 + h2], aH, bb[n2][h2 * 2], bb[n2][h2 * 2 + 1]);
        }
    }

    int qr = lane >> 2;
    int qc = (lane & 3) * 2;
    #pragma unroll
    for (int nt = 0; nt < 8; nt++) {
        float* c = acc[nt];
        #pragma unroll
        for (int half = 0; half < 2; half++) {
            int row = b * Nn + i0 + wm + qr + half * 8;
            int col = h * HS + nt * 8 + qc;
            size_t off = (size_t)row * Dd + col;
            float2 xv = *(const float2*)&x[off];
            float o0 = c[half * 2 + 0] + xv.x;
            float o1 = c[half * 2 + 1] + xv.y;
            *(float2*)&g_x2[off] = make_float2(o0, o1);
            *(u32*)&g_ah[off] = pack_h2(__float2half_rn(o0), __float2half_rn(o1));
        }
    }
}

extern "C" void kernel_launch(void* const* d_in, const int* in_sizes, int n_in,
                              void* d_out, int out_size) {
    const float* x         = (const float*)d_in[0];
    const float* ln1_scale = (const float*)d_in[1];
    const float* ln1_bias  = (const float*)d_in[2];
    const float* Wv        = (const float*)d_in[3];
    const float* alpha     = (const float*)d_in[4];
    const float* Wf        = (const float*)d_in[5];
    const float* bf        = (const float*)d_in[6];
    const float* lnf_scale = (const float*)d_in[7];
    const float* lnf_bias  = (const float*)d_in[8];
    float* out = (float*)d_out;

    float *t;
    h16 *wh, *v;
    cudaGetSymbolAddress((void**)&t,  g_t);
    cudaGetSymbolAddress((void**)&wh, g_wh);
    cudaGetSymbolAddress((void**)&v,  g_v);

    const int GSMEM = GSMEM_HW * (int)sizeof(h16);   // 56832
    const int CSMEM = CSMEM_HW * (int)sizeof(h16);   // 27648
    cudaFuncSetAttribute((const void*)gemm_f16<0>, cudaFuncAttributeMaxDynamicSharedMemorySize, GSMEM);
    cudaFuncSetAttribute((const void*)gemm_f16<1>, cudaFuncAttributeMaxDynamicSharedMemorySize, GSMEM);
    cudaFuncSetAttribute((const void*)circ_k, cudaFuncAttributeMaxDynamicSharedMemorySize, CSMEM);

    dim3 ggrid(Dd / 128, ROWS / 128);

    wsplit_wv_k<<<(D2 + 255) / 256, 256>>>(Wv);
    wsplit_wf_k<<<(2 * D2 + 255) / 256, 256>>>(Wf);
    // xn = LN(x) -> fp16
    ln_k<0, 1, 0><<<ROWS, 256>>>(x, ln1_scale, ln1_bias, nullptr);
    // v = xn @ Wcat -> fp16
    gemm_f16<1><<<ggrid, 256, GSMEM>>>(wh, nullptr, nullptr, v, ROWS, Dd, Dd);
    // x2 = x + circ(alpha, v)  -> f32 + fp16
    circ_k<<<dim3(Nn / 128, Hh, Bb), 256, CSMEM>>>(alpha, x);
    // FFN0: t = x2 @ Wf0 + bf0 (1-term)
    gemm_f16<0><<<ggrid, 256, GSMEM>>>(wh + D2, bf, t, nullptr, ROWS, Dd, Dd);
    // z0 = swish(LN(t)) -> fp16
    ln_k<1, 1, 0><<<ROWS, 256>>>(t, lnf_scale, lnf_bias, nullptr);
    // FFN1: t = z0 @ Wf1 + bf1 (1-term)
    gemm_f16<0><<<ggrid, 256, GSMEM>>>(wh + 2 * D2, bf + Dd, t, nullptr, ROWS, Dd, Dd);
    // z1 = swish(LN(t)); out = log_cosh(z1 + x2)
    ln_k<1, 0, 1><<<ROWS, 256>>>(t, lnf_scale + Dd, lnf_bias + Dd, out);
}